// round 11
// baseline (speedup 1.0000x reference)
#include <cuda_runtime.h>
#include <cuda_bf16.h>
#include <cstdint>

// Problem constants
#define T_ 8
#define L_ 8
#define N_ 500
#define D_ 64
#define K_ 12
#define S_ 2
#define RLN (L_*N_)          // 4000
#define R_ (T_*L_*N_)        // 32000 rows of (t,l,n)
#define ELEMS (R_*D_)        // 2048000

typedef unsigned long long ull;

// ---------------- scratch buffers (no allocation allowed) ----------------
__device__ float g_dyn[ELEMS];          // all_dyn (T,L,N,D)
__device__ float g_q6[6][ELEMS];        // q, then att (in place)
__device__ float g_k6[6][ELEMS];        // k per (branch,graph)
__device__ float g_x6[6][ELEMS];        // attention output per (branch,graph)
__device__ float g_h[T_*N_];            // LSTM h_last

__device__ __forceinline__ float sigf(float x) {
    return 1.f / (1.f + __expf(-x));
}

// packed dual-fp32 FMA: acc.{lo,hi} += a.{lo,hi} * b.{lo,hi}
__device__ __forceinline__ void fma2(ull& acc, ull a, ull b) {
    asm("fma.rn.f32x2 %0, %1, %2, %0;" : "+l"(acc) : "l"(a), "l"(b));
}
__device__ __forceinline__ float lo32(ull v) { return __uint_as_float((unsigned)v); }
__device__ __forceinline__ float hi32(ull v) { return __uint_as_float((unsigned)(v >> 32)); }
__device__ __forceinline__ float hadd2(ull v) { return lo32(v) + hi32(v); }

// =====================================================================
// 1. evolution scan: grid 250, block 256. (R6, unchanged)
// =====================================================================
__global__ void evo_kernel(const float* __restrict__ stat,
                           const float* __restrict__ thre,
                           const float* __restrict__ dynn,
                           const float* __restrict__ w1,
                           float* __restrict__ out_nowfinal,
                           float* __restrict__ out_diffs) {
    __shared__ float w1_s[128 * 64];      // natural: w1_s[d*64+e]
    __shared__ float now_s[16][64];
    __shared__ float st_s[16][64];
    __shared__ float th_s[16];
    int tid = threadIdx.x;
    for (int i = tid; i < 8192; i += 256) w1_s[i] = w1[i];
    int e = tid & 63, grp = tid >> 6;
    int row0 = blockIdx.x * 16;
#pragma unroll
    for (int i = 0; i < 4; i++) {
        int r = grp * 4 + i;
        float v = dynn[(size_t)(row0 + r) * 64 + e];
        now_s[r][e] = v;
        g_dyn[(size_t)(row0 + r) * 64 + e] = v;   // all_dyn[t=0]
    }
    __syncthreads();

    for (int t = 1; t < T_; t++) {
        size_t base = (size_t)t * RLN + row0;
        ((float4*)st_s)[tid] = ((const float4*)(stat + base * 64))[tid];
        if (tid < 16) th_s[tid] = thre[base + tid];
        __syncthreads();

        float sum[4] = {0.f, 0.f, 0.f, 0.f};
#pragma unroll 4
        for (int d = 0; d < 64; d += 4) {
            float wn0 = w1_s[(d + 0) * 64 + e];
            float wn1 = w1_s[(d + 1) * 64 + e];
            float wn2 = w1_s[(d + 2) * 64 + e];
            float wn3 = w1_s[(d + 3) * 64 + e];
            float ws0 = w1_s[(64 + d + 0) * 64 + e];
            float ws1 = w1_s[(64 + d + 1) * 64 + e];
            float ws2 = w1_s[(64 + d + 2) * 64 + e];
            float ws3 = w1_s[(64 + d + 3) * 64 + e];
#pragma unroll
            for (int i = 0; i < 4; i++) {
                int r = grp * 4 + i;
                float4 nv = *(float4*)&now_s[r][d];
                float4 sv = *(float4*)&st_s[r][d];
                sum[i] = fmaf(nv.x, wn0, sum[i]); sum[i] = fmaf(nv.y, wn1, sum[i]);
                sum[i] = fmaf(nv.z, wn2, sum[i]); sum[i] = fmaf(nv.w, wn3, sum[i]);
                sum[i] = fmaf(sv.x, ws0, sum[i]); sum[i] = fmaf(sv.y, ws1, sum[i]);
                sum[i] = fmaf(sv.z, ws2, sum[i]); sum[i] = fmaf(sv.w, ws3, sum[i]);
            }
        }
        float vals[4];
#pragma unroll
        for (int i = 0; i < 4; i++) {
            int r = grp * 4 + i;
            float th = th_s[r];
            float nv = now_s[r][e];
            float val = sigf(sum[i] * th + nv * (1.f - th));
            vals[i] = val;
            g_dyn[(base + r) * 64 + e] = val;
            out_diffs[((size_t)(t - 1) * RLN + row0 + r) * 64 + e] = val - nv;
            if (t == T_ - 1) out_nowfinal[(size_t)(row0 + r) * 64 + e] = val;
        }
        __syncthreads();
#pragma unroll
        for (int i = 0; i < 4; i++) now_s[grp * 4 + i][e] = vals[i];
        __syncthreads();
    }
}

// =====================================================================
// K-PACKED GEMM building blocks (f32x2 over reduction dim, zero dup movs)
// X natural [rows][64] in smem; W transposed [c][k] pitch 68 in smem.
// =====================================================================
#define WT_PITCH 68

// load WT[c0..c0+63][0..63] from natural w[k][c] via coalesced gmem reads
__device__ __forceinline__ void load_wt64(float* WT, const float* __restrict__ w,
                                          int c0, int tid) {
#pragma unroll
    for (int f = 0; f < 4; f++) {
        int gidx = f * 256 + tid;            // 0..1023
        int c = gidx & 63, k4 = gidx >> 6;   // k4 0..15
        float4 v;
        v.x = w[(4 * k4 + 0) * 64 + c];
        v.y = w[(4 * k4 + 1) * 64 + c];
        v.z = w[(4 * k4 + 2) * 64 + c];
        v.w = w[(4 * k4 + 3) * 64 + c];
        *(float4*)&WT[(c0 + c) * WT_PITCH + 4 * k4] = v;
    }
}

// =====================================================================
// 2. pass1 v3: q/k GEMM k-packed. grid 6000 (6bg x 1000), block 256,
//    32 rows/block, 4 rows x 4 cols per thread (16 ull accs).
//    smem: X[32][64] (8KB) + WT[128][68] (34.8KB) = 43008 B.
// =====================================================================
#define P1_SMEM ((2048 + 128 * WT_PITCH) * 4)   // 43008

__global__ void __launch_bounds__(256)
pass1_kernel(const float* __restrict__ stat,
             const float* __restrict__ wq_all,
             const float* __restrict__ wk_all) {
    extern __shared__ float sm[];
    float* X = sm;                   // [32][64] natural
    float* WT = sm + 2048;           // [128][68]: q cols 0-63, k cols 64-127
    int tid = threadIdx.x;
    int bg = blockIdx.x / 1000;
    int blk = blockIdx.x - bg * 1000;

    const float* src = (bg < 3) ? (const float*)g_dyn : stat;
    const float* x = src + (size_t)blk * 2048;
    for (int i = tid; i < 2048; i += 256) X[i] = x[i];
    load_wt64(WT, wq_all + (size_t)(bg * 2) * 4096, 0, tid);
    load_wt64(WT + 64 * WT_PITCH, wk_all + (size_t)(bg * 2) * 4096, 0, tid);
    __syncthreads();

    int tx = tid & 31, ty = tid >> 5;
    int r0 = ty * 4;
    ull aq[4][2], ak[4][2];
#pragma unroll
    for (int r = 0; r < 4; r++) { aq[r][0] = aq[r][1] = ak[r][0] = ak[r][1] = 0ull; }

#pragma unroll 4
    for (int k4 = 0; k4 < 16; k4++) {
        ulonglong2 a0 = *(const ulonglong2*)&X[(r0 + 0) * 64 + 4 * k4];
        ulonglong2 a1 = *(const ulonglong2*)&X[(r0 + 1) * 64 + 4 * k4];
        ulonglong2 a2 = *(const ulonglong2*)&X[(r0 + 2) * 64 + 4 * k4];
        ulonglong2 a3 = *(const ulonglong2*)&X[(r0 + 3) * 64 + 4 * k4];
        ulonglong2 wq0 = *(const ulonglong2*)&WT[tx * WT_PITCH + 4 * k4];
        ulonglong2 wq1 = *(const ulonglong2*)&WT[(tx + 32) * WT_PITCH + 4 * k4];
        ulonglong2 wk0 = *(const ulonglong2*)&WT[(64 + tx) * WT_PITCH + 4 * k4];
        ulonglong2 wk1 = *(const ulonglong2*)&WT[(96 + tx) * WT_PITCH + 4 * k4];
        fma2(aq[0][0], a0.x, wq0.x); fma2(aq[0][0], a0.y, wq0.y);
        fma2(aq[0][1], a0.x, wq1.x); fma2(aq[0][1], a0.y, wq1.y);
        fma2(ak[0][0], a0.x, wk0.x); fma2(ak[0][0], a0.y, wk0.y);
        fma2(ak[0][1], a0.x, wk1.x); fma2(ak[0][1], a0.y, wk1.y);
        fma2(aq[1][0], a1.x, wq0.x); fma2(aq[1][0], a1.y, wq0.y);
        fma2(aq[1][1], a1.x, wq1.x); fma2(aq[1][1], a1.y, wq1.y);
        fma2(ak[1][0], a1.x, wk0.x); fma2(ak[1][0], a1.y, wk0.y);
        fma2(ak[1][1], a1.x, wk1.x); fma2(ak[1][1], a1.y, wk1.y);
        fma2(aq[2][0], a2.x, wq0.x); fma2(aq[2][0], a2.y, wq0.y);
        fma2(aq[2][1], a2.x, wq1.x); fma2(aq[2][1], a2.y, wq1.y);
        fma2(ak[2][0], a2.x, wk0.x); fma2(ak[2][0], a2.y, wk0.y);
        fma2(ak[2][1], a2.x, wk1.x); fma2(ak[2][1], a2.y, wk1.y);
        fma2(aq[3][0], a3.x, wq0.x); fma2(aq[3][0], a3.y, wq0.y);
        fma2(aq[3][1], a3.x, wq1.x); fma2(aq[3][1], a3.y, wq1.y);
        fma2(ak[3][0], a3.x, wk0.x); fma2(ak[3][0], a3.y, wk0.y);
        fma2(ak[3][1], a3.x, wk1.x); fma2(ak[3][1], a3.y, wk1.y);
    }

    float* qdst = g_q6[bg];
    float* kdst = g_k6[bg];
    size_t rowbase = (size_t)blk * 32 + r0;
#pragma unroll
    for (int r = 0; r < 4; r++) {
        size_t ro = (rowbase + r) * 64;
        qdst[ro + tx]      = hadd2(aq[r][0]);
        qdst[ro + tx + 32] = hadd2(aq[r][1]);
        kdst[ro + tx]      = hadd2(ak[r][0]);
        kdst[ro + tx + 32] = hadd2(ak[r][1]);
    }
}

// =====================================================================
// 3. pass2a: gather + softmax + weighted sum. (R8, unchanged)
// =====================================================================
#define KS_FLOATS (N_ * 64)                     // 32000 floats = 128000 B
#define P2A_SMEM (KS_FLOATS * 4)

__global__ void __launch_bounds__(512)
pass2a_kernel(const int* __restrict__ n0,
              const int* __restrict__ n1,
              const int* __restrict__ n2) {
    extern __shared__ float smf[];
    float* k_s = smf;                           // [500][64] natural
    int tid = threadIdx.x;
    int bg = blockIdx.x / 64;
    int tl = blockIdx.x - bg * 64;
    int gi3 = bg % 3;
    const int* neigh = (gi3 == 0) ? n0 : (gi3 == 1) ? n1 : n2;

    float* qb = g_q6[bg] + (size_t)tl * N_ * 64;      // read q, write att
    const float* kb = g_k6[bg] + (size_t)tl * N_ * 64;

    {
        const float4* kb4 = (const float4*)kb;
        float4* ks4 = (float4*)k_s;
        for (int i = tid; i < 8000; i += 512) ks4[i] = kb4[i];
    }
    __syncthreads();

    int w = tid >> 5, lane = tid & 31;
    int half = lane >> 4, l16 = lane & 15;

    for (int it = 0; it < 8; it++) {
        int rw0 = it * 64 + w * 4;
        if (rw0 < N_) {
#pragma unroll
            for (int pr = 0; pr < 2; pr++) {
                int n = rw0 + pr * 2 + half;
                float4 q = *(const float4*)&qb[(size_t)n * 64 + l16 * 4];
                float dots[K_];
                float4 kv[K_];
#pragma unroll
                for (int j = 0; j < K_; j++) {
                    int nb = __ldg(&neigh[n * K_ + j]);
                    kv[j] = *(const float4*)&k_s[nb * 64 + l16 * 4];
                    float d = q.x * kv[j].x + q.y * kv[j].y + q.z * kv[j].z + q.w * kv[j].w;
                    d += __shfl_xor_sync(0xffffffffu, d, 8);
                    d += __shfl_xor_sync(0xffffffffu, d, 4);
                    d += __shfl_xor_sync(0xffffffffu, d, 2);
                    d += __shfl_xor_sync(0xffffffffu, d, 1);
                    dots[j] = d;
                }
                float m = dots[0];
#pragma unroll
                for (int j = 1; j < K_; j++) m = fmaxf(m, dots[j]);
                float ssum = 0.f;
#pragma unroll
                for (int j = 0; j < K_; j++) {
                    dots[j] = __expf(dots[j] - m);
                    ssum += dots[j];
                }
                float inv = 1.f / ssum;
                float4 o = q;
#pragma unroll
                for (int j = 0; j < K_; j++) {
                    float a = dots[j] * inv;
                    o.x = fmaf(a, kv[j].x, o.x);
                    o.y = fmaf(a, kv[j].y, o.y);
                    o.z = fmaf(a, kv[j].z, o.z);
                    o.w = fmaf(a, kv[j].w, o.w);
                }
                *(float4*)&qb[(size_t)n * 64 + l16 * 4] = o;   // att in place
            }
        }
    }
}

// =====================================================================
// 4. FUSED v3: x = sigmoid(att@wd0) in smem, then q/k = x@wq1|wk1.
//    grid 6000, block 256, 32 rows/block, k-packed both GEMMs.
// =====================================================================
__global__ void __launch_bounds__(256)
fused_kernel(const float* __restrict__ wd_all,
             const float* __restrict__ wq_all,
             const float* __restrict__ wk_all) {
    extern __shared__ float smF[];
    float* X = smF;                   // [32][64] att, then x
    float* WT = smF + 2048;           // [128][68]
    int tid = threadIdx.x;
    int bg = blockIdx.x / 1000;
    int blk = blockIdx.x - bg * 1000;

    const float* att = g_q6[bg] + (size_t)blk * 2048;
    for (int i = tid; i < 2048; i += 256) X[i] = att[i];
    load_wt64(WT, wd_all + (size_t)(bg * 2) * 4096, 0, tid);
    __syncthreads();

    int tx = tid & 31, ty = tid >> 5;
    int r0 = ty * 4;

    // ---- phase A: att @ wd0 ----
    ull ax[4][2];
#pragma unroll
    for (int r = 0; r < 4; r++) { ax[r][0] = 0ull; ax[r][1] = 0ull; }
#pragma unroll 4
    for (int k4 = 0; k4 < 16; k4++) {
        ulonglong2 a0 = *(const ulonglong2*)&X[(r0 + 0) * 64 + 4 * k4];
        ulonglong2 a1 = *(const ulonglong2*)&X[(r0 + 1) * 64 + 4 * k4];
        ulonglong2 a2 = *(const ulonglong2*)&X[(r0 + 2) * 64 + 4 * k4];
        ulonglong2 a3 = *(const ulonglong2*)&X[(r0 + 3) * 64 + 4 * k4];
        ulonglong2 w0 = *(const ulonglong2*)&WT[tx * WT_PITCH + 4 * k4];
        ulonglong2 w1 = *(const ulonglong2*)&WT[(tx + 32) * WT_PITCH + 4 * k4];
        fma2(ax[0][0], a0.x, w0.x); fma2(ax[0][0], a0.y, w0.y);
        fma2(ax[0][1], a0.x, w1.x); fma2(ax[0][1], a0.y, w1.y);
        fma2(ax[1][0], a1.x, w0.x); fma2(ax[1][0], a1.y, w0.y);
        fma2(ax[1][1], a1.x, w1.x); fma2(ax[1][1], a1.y, w1.y);
        fma2(ax[2][0], a2.x, w0.x); fma2(ax[2][0], a2.y, w0.y);
        fma2(ax[2][1], a2.x, w1.x); fma2(ax[2][1], a2.y, w1.y);
        fma2(ax[3][0], a3.x, w0.x); fma2(ax[3][0], a3.y, w0.y);
        fma2(ax[3][1], a3.x, w1.x); fma2(ax[3][1], a3.y, w1.y);
    }
    __syncthreads();   // all phase-A reads of X and WT complete

    // ---- phase B: store x into X, load wq1/wk1 into WT ----
#pragma unroll
    for (int r = 0; r < 4; r++) {
        X[(r0 + r) * 64 + tx]      = sigf(hadd2(ax[r][0]));
        X[(r0 + r) * 64 + tx + 32] = sigf(hadd2(ax[r][1]));
    }
    load_wt64(WT, wq_all + (size_t)(bg * 2 + 1) * 4096, 0, tid);
    load_wt64(WT + 64 * WT_PITCH, wk_all + (size_t)(bg * 2 + 1) * 4096, 0, tid);
    __syncthreads();

    // ---- phase C: q/k GEMM ----
    ull aq[4][2], ak[4][2];
#pragma unroll
    for (int r = 0; r < 4; r++) { aq[r][0] = aq[r][1] = ak[r][0] = ak[r][1] = 0ull; }
#pragma unroll 4
    for (int k4 = 0; k4 < 16; k4++) {
        ulonglong2 a0 = *(const ulonglong2*)&X[(r0 + 0) * 64 + 4 * k4];
        ulonglong2 a1 = *(const ulonglong2*)&X[(r0 + 1) * 64 + 4 * k4];
        ulonglong2 a2 = *(const ulonglong2*)&X[(r0 + 2) * 64 + 4 * k4];
        ulonglong2 a3 = *(const ulonglong2*)&X[(r0 + 3) * 64 + 4 * k4];
        ulonglong2 wq0 = *(const ulonglong2*)&WT[tx * WT_PITCH + 4 * k4];
        ulonglong2 wq1 = *(const ulonglong2*)&WT[(tx + 32) * WT_PITCH + 4 * k4];
        ulonglong2 wk0 = *(const ulonglong2*)&WT[(64 + tx) * WT_PITCH + 4 * k4];
        ulonglong2 wk1 = *(const ulonglong2*)&WT[(96 + tx) * WT_PITCH + 4 * k4];
        fma2(aq[0][0], a0.x, wq0.x); fma2(aq[0][0], a0.y, wq0.y);
        fma2(aq[0][1], a0.x, wq1.x); fma2(aq[0][1], a0.y, wq1.y);
        fma2(ak[0][0], a0.x, wk0.x); fma2(ak[0][0], a0.y, wk0.y);
        fma2(ak[0][1], a0.x, wk1.x); fma2(ak[0][1], a0.y, wk1.y);
        fma2(aq[1][0], a1.x, wq0.x); fma2(aq[1][0], a1.y, wq0.y);
        fma2(aq[1][1], a1.x, wq1.x); fma2(aq[1][1], a1.y, wq1.y);
        fma2(ak[1][0], a1.x, wk0.x); fma2(ak[1][0], a1.y, wk0.y);
        fma2(ak[1][1], a1.x, wk1.x); fma2(ak[1][1], a1.y, wk1.y);
        fma2(aq[2][0], a2.x, wq0.x); fma2(aq[2][0], a2.y, wq0.y);
        fma2(aq[2][1], a2.x, wq1.x); fma2(aq[2][1], a2.y, wq1.y);
        fma2(ak[2][0], a2.x, wk0.x); fma2(ak[2][0], a2.y, wk0.y);
        fma2(ak[2][1], a2.x, wk1.x); fma2(ak[2][1], a2.y, wk1.y);
        fma2(aq[3][0], a3.x, wq0.x); fma2(aq[3][0], a3.y, wq0.y);
        fma2(aq[3][1], a3.x, wq1.x); fma2(aq[3][1], a3.y, wq1.y);
        fma2(ak[3][0], a3.x, wk0.x); fma2(ak[3][0], a3.y, wk0.y);
        fma2(ak[3][1], a3.x, wk1.x); fma2(ak[3][1], a3.y, wk1.y);
    }

    float* qdst = g_q6[bg];
    float* kdst = g_k6[bg];
    size_t rowbase = (size_t)blk * 32 + r0;
#pragma unroll
    for (int r = 0; r < 4; r++) {
        size_t ro = (rowbase + r) * 64;
        qdst[ro + tx]      = hadd2(aq[r][0]);
        qdst[ro + tx + 32] = hadd2(aq[r][1]);
        kdst[ro + tx]      = hadd2(ak[r][0]);
        kdst[ro + tx + 32] = hadd2(ak[r][1]);
    }
}

// =====================================================================
// 5. pass2b v3: x = sigmoid(att @ wd1). grid 6000, block 256, k-packed.
//    smem: X[32][64] + WT[64][68] = 25600 B.
// =====================================================================
#define P2B_SMEM ((2048 + 64 * WT_PITCH) * 4)   // 25600

__global__ void __launch_bounds__(256)
pass2b_kernel(const float* __restrict__ wd_all) {
    extern __shared__ float sm2[];
    float* X = sm2;                  // [32][64]
    float* WT = sm2 + 2048;          // [64][68]
    int tid = threadIdx.x;
    int bg = blockIdx.x / 1000;
    int blk = blockIdx.x - bg * 1000;

    const float* att = g_q6[bg] + (size_t)blk * 2048;
    for (int i = tid; i < 2048; i += 256) X[i] = att[i];
    load_wt64(WT, wd_all + (size_t)(bg * 2 + 1) * 4096, 0, tid);
    __syncthreads();

    int tx = tid & 31, ty = tid >> 5;
    int r0 = ty * 4;
    ull ax[4][2];
#pragma unroll
    for (int r = 0; r < 4; r++) { ax[r][0] = 0ull; ax[r][1] = 0ull; }

#pragma unroll 4
    for (int k4 = 0; k4 < 16; k4++) {
        ulonglong2 a0 = *(const ulonglong2*)&X[(r0 + 0) * 64 + 4 * k4];
        ulonglong2 a1 = *(const ulonglong2*)&X[(r0 + 1) * 64 + 4 * k4];
        ulonglong2 a2 = *(const ulonglong2*)&X[(r0 + 2) * 64 + 4 * k4];
        ulonglong2 a3 = *(const ulonglong2*)&X[(r0 + 3) * 64 + 4 * k4];
        ulonglong2 w0 = *(const ulonglong2*)&WT[tx * WT_PITCH + 4 * k4];
        ulonglong2 w1 = *(const ulonglong2*)&WT[(tx + 32) * WT_PITCH + 4 * k4];
        fma2(ax[0][0], a0.x, w0.x); fma2(ax[0][0], a0.y, w0.y);
        fma2(ax[0][1], a0.x, w1.x); fma2(ax[0][1], a0.y, w1.y);
        fma2(ax[1][0], a1.x, w0.x); fma2(ax[1][0], a1.y, w0.y);
        fma2(ax[1][1], a1.x, w1.x); fma2(ax[1][1], a1.y, w1.y);
        fma2(ax[2][0], a2.x, w0.x); fma2(ax[2][0], a2.y, w0.y);
        fma2(ax[2][1], a2.x, w1.x); fma2(ax[2][1], a2.y, w1.y);
        fma2(ax[3][0], a3.x, w0.x); fma2(ax[3][0], a3.y, w0.y);
        fma2(ax[3][1], a3.x, w1.x); fma2(ax[3][1], a3.y, w1.y);
    }

    float* xdst = g_x6[bg] + (size_t)blk * 2048;
#pragma unroll
    for (int r = 0; r < 4; r++) {
        xdst[(size_t)(r0 + r) * 64 + tx]      = sigf(hadd2(ax[r][0]));
        xdst[(size_t)(r0 + r) * 64 + tx + 32] = sigf(hadd2(ax[r][1]));
    }
}

// =====================================================================
// 6. LSTM over L with FUSED mix: warp per (t,n). grid 500 x 256. (R7)
// =====================================================================
__global__ void lstm_kernel(const float* __restrict__ convw,
                            const float* __restrict__ convb,
                            const float* __restrict__ wmix) {
    __shared__ float cw[4 * 129];
    __shared__ float cb[4];
    __shared__ float wm_s[2 * 192];
    int tid = threadIdx.x;
    for (int i = tid; i < 516; i += 256) cw[i] = convw[i];
    if (tid < 4) cb[tid] = convb[tid];
    if (tid < 128) {
        wm_s[tid] = wmix[tid];
        wm_s[tid + 128] = wmix[tid + 128];
        wm_s[tid + 256] = wmix[tid + 256];
    }
    __syncthreads();
    int gw = blockIdx.x * 8 + (tid >> 5);
    int lane = tid & 31;
    int t = gw / N_, n = gw % N_;
    int b = lane >> 4;
    int dl = (lane & 15) * 4;
    int dbase = b * 64 + dl;
    float wreg[4][4], wh[4], bb[4];
#pragma unroll
    for (int i = 0; i < 4; i++) {
#pragma unroll
        for (int q = 0; q < 4; q++) wreg[i][q] = cw[i * 129 + dbase + q];
        wh[i] = cw[i * 129 + 128];
        bb[i] = cb[i];
    }
    const float* wm = wm_s + b * 192;
    float4 m0 = *(const float4*)&wm[dl];
    float4 m1 = *(const float4*)&wm[64 + dl];
    float4 m2 = *(const float4*)&wm[128 + dl];

    float h = 0.f, c = 0.f;
    for (int l = 0; l < L_; l++) {
        size_t off = (((size_t)t * L_ + l) * N_ + n) * 64 + dl;
        float4 x0 = *(const float4*)&g_x6[b * 3 + 0][off];
        float4 x1 = *(const float4*)&g_x6[b * 3 + 1][off];
        float4 x2 = *(const float4*)&g_x6[b * 3 + 2][off];
        float4 xin;
        xin.x = sigf(x0.x * m0.x + x1.x * m1.x + x2.x * m2.x);
        xin.y = sigf(x0.y * m0.y + x1.y * m1.y + x2.y * m2.y);
        xin.z = sigf(x0.z * m0.z + x1.z * m1.z + x2.z * m2.z);
        xin.w = sigf(x0.w * m0.w + x1.w * m1.w + x2.w * m2.w);
        float s[4];
#pragma unroll
        for (int i = 0; i < 4; i++) {
            s[i] = xin.x * wreg[i][0] + xin.y * wreg[i][1] +
                   xin.z * wreg[i][2] + xin.w * wreg[i][3];
#pragma unroll
            for (int o = 16; o; o >>= 1)
                s[i] += __shfl_xor_sync(0xffffffffu, s[i], o);
        }
        float gi = sigf(s[0] + h * wh[0] + bb[0]);
        float gf = sigf(s[1] + h * wh[1] + bb[1]);
        float go = sigf(s[2] + h * wh[2] + bb[2]);
        float gg = tanhf(s[3] + h * wh[3] + bb[3]);
        c = gf * c + gi * gg;
        h = go * tanhf(c);
    }
    if (lane == 0) g_h[t * N_ + n] = h;
}

// =====================================================================
// 7. final projection: grid T_, block 512
// =====================================================================
__global__ void final_kernel(const float* __restrict__ finw,
                             const float* __restrict__ finb,
                             float* __restrict__ out) {
    __shared__ float hs[500];
    int t = blockIdx.x, tid = threadIdx.x;
    if (tid < 500) hs[tid] = g_h[t * N_ + tid];
    __syncthreads();
    if (tid < 500) {
        float acc = finb[tid];
        const float4* wr = (const float4*)(finw + (size_t)tid * 500);
#pragma unroll 5
        for (int m4 = 0; m4 < 125; m4++) {
            float4 wv = wr[m4];
            acc = fmaf(hs[m4 * 4 + 0], wv.x, acc);
            acc = fmaf(hs[m4 * 4 + 1], wv.y, acc);
            acc = fmaf(hs[m4 * 4 + 2], wv.z, acc);
            acc = fmaf(hs[m4 * 4 + 3], wv.w, acc);
        }
        out[t * N_ + tid] = sigf(acc);
    }
}

// ---------------- launcher ----------------
extern "C" void kernel_launch(void* const* d_in, const int* in_sizes, int n_in,
                              void* d_out, int out_size) {
    const float* stat = (const float*)d_in[0];
    const float* thre = (const float*)d_in[1];
    const float* dynn = (const float*)d_in[2];
    const int* npoi = (const int*)d_in[3];
    const int* nroad = (const int*)d_in[4];
    const int* nrec = (const int*)d_in[5];
    const float* w1 = (const float*)d_in[6];
    const float* wq = (const float*)d_in[7];
    const float* wk = (const float*)d_in[8];
    const float* wdm = (const float*)d_in[9];
    const float* wmix = (const float*)d_in[10];
    const float* convw = (const float*)d_in[11];
    const float* convb = (const float*)d_in[12];
    const float* finw = (const float*)d_in[13];
    const float* finb = (const float*)d_in[14];

    float* out = (float*)d_out;
    float* out_scores = out;                          // (T,N)       4000
    float* out_nowfinal = out + T_ * N_;              // (L,N,D)     256000
    float* out_diffs = out + T_ * N_ + L_ * N_ * D_;  // (T-1,L,N,D) 1792000

    cudaFuncSetAttribute(pass1_kernel,
                         cudaFuncAttributeMaxDynamicSharedMemorySize, P1_SMEM);
    cudaFuncSetAttribute(fused_kernel,
                         cudaFuncAttributeMaxDynamicSharedMemorySize, P1_SMEM);
    cudaFuncSetAttribute(pass2a_kernel,
                         cudaFuncAttributeMaxDynamicSharedMemorySize, P2A_SMEM);
    cudaFuncSetAttribute(pass2b_kernel,
                         cudaFuncAttributeMaxDynamicSharedMemorySize, P2B_SMEM);

    evo_kernel<<<250, 256>>>(stat, thre, dynn, w1, out_nowfinal, out_diffs);

    pass1_kernel<<<6000, 256, P1_SMEM>>>(stat, wq, wk);        // s=0
    pass2a_kernel<<<384, 512, P2A_SMEM>>>(npoi, nroad, nrec);  // s=0
    fused_kernel<<<6000, 256, P1_SMEM>>>(wdm, wq, wk);         // x(s=0)+qk(s=1)
    pass2a_kernel<<<384, 512, P2A_SMEM>>>(npoi, nroad, nrec);  // s=1
    pass2b_kernel<<<6000, 256, P2B_SMEM>>>(wdm);               // s=1 -> g_x6

    lstm_kernel<<<500, 256>>>(convw, convb, wmix);
    final_kernel<<<T_, 512>>>(finw, finb, out_scores);
}

// round 12
// speedup vs baseline: 1.0974x; 1.0974x over previous
#include <cuda_runtime.h>
#include <cuda_bf16.h>
#include <cstdint>

// Problem constants
#define T_ 8
#define L_ 8
#define N_ 500
#define D_ 64
#define K_ 12
#define S_ 2
#define RLN (L_*N_)          // 4000
#define R_ (T_*L_*N_)        // 32000 rows of (t,l,n)
#define ELEMS (R_*D_)        // 2048000

typedef unsigned long long ull;

// ---------------- scratch buffers (no allocation allowed) ----------------
__device__ float g_dyn[ELEMS];          // all_dyn (T,L,N,D)
__device__ float g_q6[6][ELEMS];        // q, then att (in place)
__device__ float g_k6[6][ELEMS];        // k per (branch,graph)
__device__ float g_x6[6][ELEMS];        // attention output per (branch,graph)
__device__ float g_h[T_*N_];            // LSTM h_last

__device__ __forceinline__ float sigf(float x) {
    return 1.f / (1.f + __expf(-x));
}

// packed dual-fp32 FMA: acc.{lo,hi} += a.{lo,hi} * b.{lo,hi}
__device__ __forceinline__ void fma2(ull& acc, ull a, ull b) {
    asm("fma.rn.f32x2 %0, %1, %2, %0;" : "+l"(acc) : "l"(a), "l"(b));
}
__device__ __forceinline__ float lo32(ull v) { return __uint_as_float((unsigned)v); }
__device__ __forceinline__ float hi32(ull v) { return __uint_as_float((unsigned)(v >> 32)); }
__device__ __forceinline__ ull dup2(float a) {
    ull r; unsigned u = __float_as_uint(a);
    asm("mov.b64 %0, {%1, %1};" : "=l"(r) : "r"(u));
    return r;
}

// =====================================================================
// 1. evolution scan: grid 250, block 256. (R6, unchanged)
// =====================================================================
__global__ void evo_kernel(const float* __restrict__ stat,
                           const float* __restrict__ thre,
                           const float* __restrict__ dynn,
                           const float* __restrict__ w1,
                           float* __restrict__ out_nowfinal,
                           float* __restrict__ out_diffs) {
    __shared__ float w1_s[128 * 64];      // natural: w1_s[d*64+e]
    __shared__ float now_s[16][64];
    __shared__ float st_s[16][64];
    __shared__ float th_s[16];
    int tid = threadIdx.x;
    for (int i = tid; i < 8192; i += 256) w1_s[i] = w1[i];
    int e = tid & 63, grp = tid >> 6;
    int row0 = blockIdx.x * 16;
#pragma unroll
    for (int i = 0; i < 4; i++) {
        int r = grp * 4 + i;
        float v = dynn[(size_t)(row0 + r) * 64 + e];
        now_s[r][e] = v;
        g_dyn[(size_t)(row0 + r) * 64 + e] = v;   // all_dyn[t=0]
    }
    __syncthreads();

    for (int t = 1; t < T_; t++) {
        size_t base = (size_t)t * RLN + row0;
        ((float4*)st_s)[tid] = ((const float4*)(stat + base * 64))[tid];
        if (tid < 16) th_s[tid] = thre[base + tid];
        __syncthreads();

        float sum[4] = {0.f, 0.f, 0.f, 0.f};
#pragma unroll 4
        for (int d = 0; d < 64; d += 4) {
            float wn0 = w1_s[(d + 0) * 64 + e];
            float wn1 = w1_s[(d + 1) * 64 + e];
            float wn2 = w1_s[(d + 2) * 64 + e];
            float wn3 = w1_s[(d + 3) * 64 + e];
            float ws0 = w1_s[(64 + d + 0) * 64 + e];
            float ws1 = w1_s[(64 + d + 1) * 64 + e];
            float ws2 = w1_s[(64 + d + 2) * 64 + e];
            float ws3 = w1_s[(64 + d + 3) * 64 + e];
#pragma unroll
            for (int i = 0; i < 4; i++) {
                int r = grp * 4 + i;
                float4 nv = *(float4*)&now_s[r][d];
                float4 sv = *(float4*)&st_s[r][d];
                sum[i] = fmaf(nv.x, wn0, sum[i]); sum[i] = fmaf(nv.y, wn1, sum[i]);
                sum[i] = fmaf(nv.z, wn2, sum[i]); sum[i] = fmaf(nv.w, wn3, sum[i]);
                sum[i] = fmaf(sv.x, ws0, sum[i]); sum[i] = fmaf(sv.y, ws1, sum[i]);
                sum[i] = fmaf(sv.z, ws2, sum[i]); sum[i] = fmaf(sv.w, ws3, sum[i]);
            }
        }
        float vals[4];
#pragma unroll
        for (int i = 0; i < 4; i++) {
            int r = grp * 4 + i;
            float th = th_s[r];
            float nv = now_s[r][e];
            float val = sigf(sum[i] * th + nv * (1.f - th));
            vals[i] = val;
            g_dyn[(base + r) * 64 + e] = val;
            out_diffs[((size_t)(t - 1) * RLN + row0 + r) * 64 + e] = val - nv;
            if (t == T_ - 1) out_nowfinal[(size_t)(row0 + r) * 64 + e] = val;
        }
        __syncthreads();
#pragma unroll
        for (int i = 0; i < 4; i++) now_s[grp * 4 + i][e] = vals[i];
        __syncthreads();
    }
}

// =====================================================================
// 2. pass1 (R4/R6 exact): q/k GEMM, f32x2 col-pairs, natural W,
//    reg-dup'd A. grid 3000 (6 bg x 500), block 256. s=0 only.
// =====================================================================
#define AT_PITCH 68
#define ANAT_PITCH 65
#define W_PITCH 132
#define P1_SMEM ((64*AT_PITCH + 64*W_PITCH) * 4)    // 51200

__global__ void __launch_bounds__(256)
pass1_kernel(const float* __restrict__ stat,
             const float* __restrict__ wq_all,
             const float* __restrict__ wk_all) {
    extern __shared__ float sm[];
    float* At = sm;                      // [64][AT_PITCH]
    float* W_s = sm + 64 * AT_PITCH;     // [64][W_PITCH]
    float* A_nat = W_s;                  // transient staging [64][ANAT_PITCH]
    int tid = threadIdx.x;
    int bg = blockIdx.x / 500;
    int blk = blockIdx.x - bg * 500;

    const float* src = (bg < 3) ? (const float*)g_dyn : stat;
    const float* x = src + (size_t)blk * 64 * 64;

    for (int i = tid; i < 4096; i += 256) {
        int row = i >> 6, k = i & 63;
        A_nat[row * ANAT_PITCH + k] = x[i];
    }
    __syncthreads();
    {
        int k = tid & 63, rg = tid >> 6;
#pragma unroll
        for (int r16 = 0; r16 < 16; r16++) {
            int row = rg * 16 + r16;
            At[k * AT_PITCH + row] = A_nat[row * ANAT_PITCH + k];
        }
    }
    __syncthreads();
    {
        const float4* wq4 = (const float4*)(wq_all + (size_t)(bg * 2) * 4096);
        const float4* wk4 = (const float4*)(wk_all + (size_t)(bg * 2) * 4096);
        for (int i = tid; i < 2048; i += 256) {
            int half = i >> 10, idx = i & 1023;
            int k = idx >> 4, c4 = (idx & 15) << 2;
            float4 v = half ? wk4[idx] : wq4[idx];
            *(float4*)&W_s[k * W_PITCH + half * 64 + c4] = v;
        }
    }
    __syncthreads();

    int tx = tid & 31, ty = tid >> 5;
    ull acc[8][2];
#pragma unroll
    for (int r = 0; r < 8; r++) { acc[r][0] = 0ull; acc[r][1] = 0ull; }

#pragma unroll 4
    for (int k = 0; k < 64; k++) {
        float4 a0 = *(const float4*)&At[k * AT_PITCH + ty * 8];
        float4 a1 = *(const float4*)&At[k * AT_PITCH + ty * 8 + 4];
        const ull* wrow = (const ull*)&W_s[k * W_PITCH];
        ull wq2 = wrow[tx];
        ull wk2 = wrow[tx + 32];
        ull ad[8];
        ad[0] = dup2(a0.x); ad[1] = dup2(a0.y); ad[2] = dup2(a0.z); ad[3] = dup2(a0.w);
        ad[4] = dup2(a1.x); ad[5] = dup2(a1.y); ad[6] = dup2(a1.z); ad[7] = dup2(a1.w);
#pragma unroll
        for (int r = 0; r < 8; r++) {
            fma2(acc[r][0], ad[r], wq2);
            fma2(acc[r][1], ad[r], wk2);
        }
    }

    float* qdst = g_q6[bg];
    float* kdst = g_k6[bg];
    size_t rowbase = (size_t)blk * 64 + ty * 8;
#pragma unroll
    for (int r = 0; r < 8; r++) {
        size_t ro = (rowbase + r) * 64 + 2 * tx;
        *(float2*)&qdst[ro] = make_float2(lo32(acc[r][0]), hi32(acc[r][0]));
        *(float2*)&kdst[ro] = make_float2(lo32(acc[r][1]), hi32(acc[r][1]));
    }
}

// =====================================================================
// 3. pass2a v2: gather + softmax + weighted sum, gathers FROM L2
//    (g_k6 is L2-resident: 48 MB just written). NO smem -> high occ,
//    full waves. grid 6000 (6 bg x 1000), block 256, 32 rows/block.
//    att = q + sum a*k written IN PLACE into g_q6. Math identical to R10.
// =====================================================================
__global__ void __launch_bounds__(256)
pass2a_kernel(const int* __restrict__ n0,
              const int* __restrict__ n1,
              const int* __restrict__ n2) {
    int tid = threadIdx.x;
    int bg = blockIdx.x / 1000;
    int blk = blockIdx.x - bg * 1000;
    int gi3 = bg % 3;
    const int* neigh = (gi3 == 0) ? n0 : (gi3 == 1) ? n1 : n2;

    float* qbase = g_q6[bg];
    const float* kbase = g_k6[bg];

    int w = tid >> 5, lane = tid & 31;
    int half = lane >> 4, l16 = lane & 15;

#pragma unroll
    for (int pr = 0; pr < 2; pr++) {
        int rowid = blk * 32 + w * 4 + pr * 2 + half;
        int tl = rowid / N_;
        int n = rowid - tl * N_;
        float* qb = qbase + (size_t)tl * N_ * 64;
        const float* kb = kbase + (size_t)tl * N_ * 64;

        float4 q = *(const float4*)&qb[(size_t)n * 64 + l16 * 4];
        float dots[K_];
        float4 kv[K_];
#pragma unroll
        for (int j = 0; j < K_; j++) {
            int nb = __ldg(&neigh[n * K_ + j]);
            kv[j] = __ldg((const float4*)&kb[(size_t)nb * 64 + l16 * 4]);
            float d = q.x * kv[j].x + q.y * kv[j].y + q.z * kv[j].z + q.w * kv[j].w;
            d += __shfl_xor_sync(0xffffffffu, d, 8);
            d += __shfl_xor_sync(0xffffffffu, d, 4);
            d += __shfl_xor_sync(0xffffffffu, d, 2);
            d += __shfl_xor_sync(0xffffffffu, d, 1);
            dots[j] = d;
        }
        float m = dots[0];
#pragma unroll
        for (int j = 1; j < K_; j++) m = fmaxf(m, dots[j]);
        float ssum = 0.f;
#pragma unroll
        for (int j = 0; j < K_; j++) {
            dots[j] = __expf(dots[j] - m);
            ssum += dots[j];
        }
        float inv = 1.f / ssum;
        float4 o = q;
#pragma unroll
        for (int j = 0; j < K_; j++) {
            float a = dots[j] * inv;
            o.x = fmaf(a, kv[j].x, o.x);
            o.y = fmaf(a, kv[j].y, o.y);
            o.z = fmaf(a, kv[j].z, o.z);
            o.w = fmaf(a, kv[j].w, o.w);
        }
        *(float4*)&qb[(size_t)n * 64 + l16 * 4] = o;   // att in place
    }
}

// =====================================================================
// 4. FUSED pass2b(s=0) + pass1(s=1) (R10 exact): grid 3000, block 256.
// =====================================================================
__global__ void __launch_bounds__(256)
fused_kernel(const float* __restrict__ wd_all,
             const float* __restrict__ wq_all,
             const float* __restrict__ wk_all) {
    extern __shared__ float smF[];
    float* At = smF;                        // [64][68]
    float* W_s = smF + 64 * AT_PITCH;       // [64][132]
    float* A_nat = W_s;                     // [64][65] transient (4160 floats)
    float* wd_s = W_s + 4160;               // [64][64] natural (4096 floats)
    int tid = threadIdx.x;
    int bg = blockIdx.x / 500;
    int blk = blockIdx.x - bg * 500;

    const float* att = g_q6[bg] + (size_t)blk * 4096;
    for (int i = tid; i < 4096; i += 256) {
        int row = i >> 6, k = i & 63;
        A_nat[row * 65 + k] = att[i];
    }
    {
        const float4* wd4 = (const float4*)(wd_all + (size_t)(bg * 2) * 4096);
        for (int i = tid; i < 1024; i += 256) ((float4*)wd_s)[i] = wd4[i];
    }
    __syncthreads();
    for (int i = tid; i < 4096; i += 256) {
        int k = i >> 6, row = i & 63;
        At[k * AT_PITCH + row] = A_nat[row * 65 + k];
    }
    __syncthreads();

    int tx = tid & 31, ty = tid >> 5;
    ull accx[4][2];
#pragma unroll
    for (int p = 0; p < 4; p++) { accx[p][0] = 0ull; accx[p][1] = 0ull; }
#pragma unroll 4
    for (int k = 0; k < 64; k++) {
        const ulonglong2* ar = (const ulonglong2*)(At + k * AT_PITCH + ty * 8);
        ulonglong2 a01 = ar[0];
        ulonglong2 a23 = ar[1];
        ull w0 = dup2(wd_s[k * 64 + tx]);
        ull w1 = dup2(wd_s[k * 64 + tx + 32]);
        fma2(accx[0][0], a01.x, w0); fma2(accx[0][1], a01.x, w1);
        fma2(accx[1][0], a01.y, w0); fma2(accx[1][1], a01.y, w1);
        fma2(accx[2][0], a23.x, w0); fma2(accx[2][1], a23.x, w1);
        fma2(accx[3][0], a23.y, w0); fma2(accx[3][1], a23.y, w1);
    }
    __syncthreads();   // everyone done reading At + wd_s

#pragma unroll
    for (int p = 0; p < 4; p++) {
        int r0 = ty * 8 + 2 * p;
        *(float2*)&At[tx * AT_PITCH + r0] =
            make_float2(sigf(lo32(accx[p][0])), sigf(hi32(accx[p][0])));
        *(float2*)&At[(tx + 32) * AT_PITCH + r0] =
            make_float2(sigf(lo32(accx[p][1])), sigf(hi32(accx[p][1])));
    }
    {
        const float4* wq4 = (const float4*)(wq_all + (size_t)(bg * 2 + 1) * 4096);
        const float4* wk4 = (const float4*)(wk_all + (size_t)(bg * 2 + 1) * 4096);
        for (int i = tid; i < 2048; i += 256) {
            int half = i >> 10, idx = i & 1023;
            int k = idx >> 4, c4 = (idx & 15) << 2;
            float4 v = half ? wk4[idx] : wq4[idx];
            *(float4*)&W_s[k * W_PITCH + half * 64 + c4] = v;
        }
    }
    __syncthreads();

    ull acc[8][2];
#pragma unroll
    for (int r = 0; r < 8; r++) { acc[r][0] = 0ull; acc[r][1] = 0ull; }
#pragma unroll 4
    for (int k = 0; k < 64; k++) {
        float4 a0 = *(const float4*)&At[k * AT_PITCH + ty * 8];
        float4 a1 = *(const float4*)&At[k * AT_PITCH + ty * 8 + 4];
        const ull* wrow = (const ull*)&W_s[k * W_PITCH];
        ull wq2 = wrow[tx];
        ull wk2 = wrow[tx + 32];
        ull ad[8];
        ad[0] = dup2(a0.x); ad[1] = dup2(a0.y); ad[2] = dup2(a0.z); ad[3] = dup2(a0.w);
        ad[4] = dup2(a1.x); ad[5] = dup2(a1.y); ad[6] = dup2(a1.z); ad[7] = dup2(a1.w);
#pragma unroll
        for (int r = 0; r < 8; r++) {
            fma2(acc[r][0], ad[r], wq2);
            fma2(acc[r][1], ad[r], wk2);
        }
    }

    float* qdst = g_q6[bg];
    float* kdst = g_k6[bg];
    size_t rowbase = (size_t)blk * 64 + ty * 8;
#pragma unroll
    for (int r = 0; r < 8; r++) {
        size_t ro = (rowbase + r) * 64 + 2 * tx;
        *(float2*)&qdst[ro] = make_float2(lo32(acc[r][0]), hi32(acc[r][0]));
        *(float2*)&kdst[ro] = make_float2(lo32(acc[r][1]), hi32(acc[r][1]));
    }
}

// =====================================================================
// 5. pass2b (R8 v1 exact): x = sigmoid(att @ wd). grid 3000, block 256.
// =====================================================================
#define P2B_AT 68
#define P2B_AUX_OFF (64 * P2B_AT)                 // floats
#define P2B_SMEM ((64 * P2B_AT + 64 * 65) * 4)    // 34048

__global__ void __launch_bounds__(256)
pass2b_kernel(const float* __restrict__ wd_all) {
    extern __shared__ float sm2[];
    float* At = sm2;                    // [64][68] transposed att
    float* aux = sm2 + P2B_AUX_OFF;     // x_nat [64][65], then wd [64][64]
    int tid = threadIdx.x;
    int bg = blockIdx.x / 500;
    int blk = blockIdx.x - bg * 500;

    const float* att = g_q6[bg] + (size_t)blk * 4096;
    for (int i = tid; i < 4096; i += 256) {
        int row = i >> 6, k = i & 63;
        aux[row * 65 + k] = att[i];
    }
    __syncthreads();
    for (int i = tid; i < 4096; i += 256) {
        int k = i >> 6, row = i & 63;
        At[k * P2B_AT + row] = aux[row * 65 + k];
    }
    __syncthreads();
    {
        const float4* wd4 = (const float4*)(wd_all + (size_t)(bg * 2 + 1) * 4096);
        for (int i = tid; i < 1024; i += 256) ((float4*)aux)[i] = wd4[i];
    }
    __syncthreads();

    int lane = tid & 31, ty = tid >> 5;
    ull acc[4][2];
#pragma unroll
    for (int p = 0; p < 4; p++) { acc[p][0] = 0ull; acc[p][1] = 0ull; }

#pragma unroll 4
    for (int k = 0; k < 64; k++) {
        const ulonglong2* ar = (const ulonglong2*)(At + k * P2B_AT + ty * 8);
        ulonglong2 a01 = ar[0];
        ulonglong2 a23 = ar[1];
        ull wd0 = dup2(aux[k * 64 + lane]);
        ull wd1 = dup2(aux[k * 64 + lane + 32]);
        fma2(acc[0][0], a01.x, wd0); fma2(acc[0][1], a01.x, wd1);
        fma2(acc[1][0], a01.y, wd0); fma2(acc[1][1], a01.y, wd1);
        fma2(acc[2][0], a23.x, wd0); fma2(acc[2][1], a23.x, wd1);
        fma2(acc[3][0], a23.y, wd0); fma2(acc[3][1], a23.y, wd1);
    }

    float* xdst = g_x6[bg] + (size_t)blk * 4096;
#pragma unroll
    for (int p = 0; p < 4; p++) {
        int r0 = ty * 8 + 2 * p;
        xdst[(size_t)r0 * 64 + lane]            = sigf(lo32(acc[p][0]));
        xdst[(size_t)(r0 + 1) * 64 + lane]      = sigf(hi32(acc[p][0]));
        xdst[(size_t)r0 * 64 + lane + 32]       = sigf(lo32(acc[p][1]));
        xdst[(size_t)(r0 + 1) * 64 + lane + 32] = sigf(hi32(acc[p][1]));
    }
}

// =====================================================================
// 6. LSTM over L with FUSED mix: warp per (t,n). grid 500 x 256. (R7)
// =====================================================================
__global__ void lstm_kernel(const float* __restrict__ convw,
                            const float* __restrict__ convb,
                            const float* __restrict__ wmix) {
    __shared__ float cw[4 * 129];
    __shared__ float cb[4];
    __shared__ float wm_s[2 * 192];
    int tid = threadIdx.x;
    for (int i = tid; i < 516; i += 256) cw[i] = convw[i];
    if (tid < 4) cb[tid] = convb[tid];
    if (tid < 128) {
        wm_s[tid] = wmix[tid];
        wm_s[tid + 128] = wmix[tid + 128];
        wm_s[tid + 256] = wmix[tid + 256];
    }
    __syncthreads();
    int gw = blockIdx.x * 8 + (tid >> 5);
    int lane = tid & 31;
    int t = gw / N_, n = gw % N_;
    int b = lane >> 4;
    int dl = (lane & 15) * 4;
    int dbase = b * 64 + dl;
    float wreg[4][4], wh[4], bb[4];
#pragma unroll
    for (int i = 0; i < 4; i++) {
#pragma unroll
        for (int q = 0; q < 4; q++) wreg[i][q] = cw[i * 129 + dbase + q];
        wh[i] = cw[i * 129 + 128];
        bb[i] = cb[i];
    }
    const float* wm = wm_s + b * 192;
    float4 m0 = *(const float4*)&wm[dl];
    float4 m1 = *(const float4*)&wm[64 + dl];
    float4 m2 = *(const float4*)&wm[128 + dl];

    float h = 0.f, c = 0.f;
    for (int l = 0; l < L_; l++) {
        size_t off = (((size_t)t * L_ + l) * N_ + n) * 64 + dl;
        float4 x0 = *(const float4*)&g_x6[b * 3 + 0][off];
        float4 x1 = *(const float4*)&g_x6[b * 3 + 1][off];
        float4 x2 = *(const float4*)&g_x6[b * 3 + 2][off];
        float4 xin;
        xin.x = sigf(x0.x * m0.x + x1.x * m1.x + x2.x * m2.x);
        xin.y = sigf(x0.y * m0.y + x1.y * m1.y + x2.y * m2.y);
        xin.z = sigf(x0.z * m0.z + x1.z * m1.z + x2.z * m2.z);
        xin.w = sigf(x0.w * m0.w + x1.w * m1.w + x2.w * m2.w);
        float s[4];
#pragma unroll
        for (int i = 0; i < 4; i++) {
            s[i] = xin.x * wreg[i][0] + xin.y * wreg[i][1] +
                   xin.z * wreg[i][2] + xin.w * wreg[i][3];
#pragma unroll
            for (int o = 16; o; o >>= 1)
                s[i] += __shfl_xor_sync(0xffffffffu, s[i], o);
        }
        float gi = sigf(s[0] + h * wh[0] + bb[0]);
        float gf = sigf(s[1] + h * wh[1] + bb[1]);
        float go = sigf(s[2] + h * wh[2] + bb[2]);
        float gg = tanhf(s[3] + h * wh[3] + bb[3]);
        c = gf * c + gi * gg;
        h = go * tanhf(c);
    }
    if (lane == 0) g_h[t * N_ + n] = h;
}

// =====================================================================
// 7. final projection: grid T_, block 512
// =====================================================================
__global__ void final_kernel(const float* __restrict__ finw,
                             const float* __restrict__ finb,
                             float* __restrict__ out) {
    __shared__ float hs[500];
    int t = blockIdx.x, tid = threadIdx.x;
    if (tid < 500) hs[tid] = g_h[t * N_ + tid];
    __syncthreads();
    if (tid < 500) {
        float acc = finb[tid];
        const float4* wr = (const float4*)(finw + (size_t)tid * 500);
#pragma unroll 5
        for (int m4 = 0; m4 < 125; m4++) {
            float4 wv = wr[m4];
            acc = fmaf(hs[m4 * 4 + 0], wv.x, acc);
            acc = fmaf(hs[m4 * 4 + 1], wv.y, acc);
            acc = fmaf(hs[m4 * 4 + 2], wv.z, acc);
            acc = fmaf(hs[m4 * 4 + 3], wv.w, acc);
        }
        out[t * N_ + tid] = sigf(acc);
    }
}

// ---------------- launcher ----------------
extern "C" void kernel_launch(void* const* d_in, const int* in_sizes, int n_in,
                              void* d_out, int out_size) {
    const float* stat = (const float*)d_in[0];
    const float* thre = (const float*)d_in[1];
    const float* dynn = (const float*)d_in[2];
    const int* npoi = (const int*)d_in[3];
    const int* nroad = (const int*)d_in[4];
    const int* nrec = (const int*)d_in[5];
    const float* w1 = (const float*)d_in[6];
    const float* wq = (const float*)d_in[7];
    const float* wk = (const float*)d_in[8];
    const float* wdm = (const float*)d_in[9];
    const float* wmix = (const float*)d_in[10];
    const float* convw = (const float*)d_in[11];
    const float* convb = (const float*)d_in[12];
    const float* finw = (const float*)d_in[13];
    const float* finb = (const float*)d_in[14];

    float* out = (float*)d_out;
    float* out_scores = out;                          // (T,N)       4000
    float* out_nowfinal = out + T_ * N_;              // (L,N,D)     256000
    float* out_diffs = out + T_ * N_ + L_ * N_ * D_;  // (T-1,L,N,D) 1792000

    cudaFuncSetAttribute(pass1_kernel,
                         cudaFuncAttributeMaxDynamicSharedMemorySize, P1_SMEM);
    cudaFuncSetAttribute(fused_kernel,
                         cudaFuncAttributeMaxDynamicSharedMemorySize, P1_SMEM);
    cudaFuncSetAttribute(pass2b_kernel,
                         cudaFuncAttributeMaxDynamicSharedMemorySize, P2B_SMEM);

    evo_kernel<<<250, 256>>>(stat, thre, dynn, w1, out_nowfinal, out_diffs);

    pass1_kernel<<<3000, 256, P1_SMEM>>>(stat, wq, wk);        // s=0
    pass2a_kernel<<<6000, 256>>>(npoi, nroad, nrec);           // s=0 (L2 gather)
    fused_kernel<<<3000, 256, P1_SMEM>>>(wdm, wq, wk);         // x(s=0)+qk(s=1)
    pass2a_kernel<<<6000, 256>>>(npoi, nroad, nrec);           // s=1 (L2 gather)
    pass2b_kernel<<<3000, 256, P2B_SMEM>>>(wdm);               // s=1 -> g_x6

    lstm_kernel<<<500, 256>>>(convw, convb, wmix);
    final_kernel<<<T_, 512>>>(finw, finb, out_scores);
}

// round 13
// speedup vs baseline: 1.1201x; 1.0207x over previous
#include <cuda_runtime.h>
#include <cuda_bf16.h>
#include <cstdint>

// Problem constants
#define T_ 8
#define L_ 8
#define N_ 500
#define D_ 64
#define K_ 12
#define S_ 2
#define RLN (L_*N_)          // 4000
#define R_ (T_*L_*N_)        // 32000 rows of (t,l,n)
#define ELEMS (R_*D_)        // 2048000

typedef unsigned long long ull;

// ---------------- scratch buffers (no allocation allowed) ----------------
__device__ float g_dyn[ELEMS];          // all_dyn (T,L,N,D)
__device__ float g_q6[6][ELEMS];        // stage-0 q
__device__ float g_k6[6][ELEMS];        // stage-0 k
__device__ float g_q6b[6][ELEMS];       // stage-1 q
__device__ float g_k6b[6][ELEMS];       // stage-1 k
__device__ float g_x6[6][ELEMS];        // final attention output
__device__ float g_h[T_*N_];            // LSTM h_last

__device__ __forceinline__ float sigf(float x) {
    return 1.f / (1.f + __expf(-x));
}

__device__ __forceinline__ void fma2(ull& acc, ull a, ull b) {
    asm("fma.rn.f32x2 %0, %1, %2, %0;" : "+l"(acc) : "l"(a), "l"(b));
}
__device__ __forceinline__ float lo32(ull v) { return __uint_as_float((unsigned)v); }
__device__ __forceinline__ float hi32(ull v) { return __uint_as_float((unsigned)(v >> 32)); }
__device__ __forceinline__ ull dup2(float a) {
    ull r; unsigned u = __float_as_uint(a);
    asm("mov.b64 %0, {%1, %1};" : "=l"(r) : "r"(u));
    return r;
}

// =====================================================================
// shared device bodies
// =====================================================================
#define AT_PITCH 68
#define XN_PITCH 68
// pass1 smem: At[64*68]=4352 + W[64*128]=8192 -> 12544 floats
#define P1_SMEM (12544 * 4)     // 50176
// kernelC/D smem: At 4352 + wd 4096 + X_nat 4352 -> 12800 floats
#define PC_SMEM (12800 * 4)     // 51200

// q/k GEMM inner (R4 frozen loop, W pitch 128). At ready, W_s ready.
__device__ __forceinline__ void qk_gemm_and_store(
    const float* At, const float* W_s, float* qdst, float* kdst,
    size_t rowbase, int tid) {
    int tx = tid & 31, ty = tid >> 5;
    ull acc[8][2];
#pragma unroll
    for (int r = 0; r < 8; r++) { acc[r][0] = 0ull; acc[r][1] = 0ull; }
#pragma unroll 4
    for (int k = 0; k < 64; k++) {
        float4 a0 = *(const float4*)&At[k * AT_PITCH + ty * 8];
        float4 a1 = *(const float4*)&At[k * AT_PITCH + ty * 8 + 4];
        const ull* wrow = (const ull*)&W_s[k * 128];
        ull wq2 = wrow[tx];
        ull wk2 = wrow[tx + 32];
        ull ad[8];
        ad[0] = dup2(a0.x); ad[1] = dup2(a0.y); ad[2] = dup2(a0.z); ad[3] = dup2(a0.w);
        ad[4] = dup2(a1.x); ad[5] = dup2(a1.y); ad[6] = dup2(a1.z); ad[7] = dup2(a1.w);
#pragma unroll
        for (int r = 0; r < 8; r++) {
            fma2(acc[r][0], ad[r], wq2);
            fma2(acc[r][1], ad[r], wk2);
        }
    }
#pragma unroll
    for (int r = 0; r < 8; r++) {
        size_t ro = (rowbase + r) * 64 + 2 * tx;
        *(float2*)&qdst[ro] = make_float2(lo32(acc[r][0]), hi32(acc[r][0]));
        *(float2*)&kdst[ro] = make_float2(lo32(acc[r][1]), hi32(acc[r][1]));
    }
}

// pass1 body: direct transposed load of X + W load + GEMM
__device__ __forceinline__ void pass1_body(
    const float* __restrict__ x, const float* __restrict__ wq,
    const float* __restrict__ wk, float* qdst, float* kdst,
    size_t rowbase, float* sm, int tid) {
    float* At = sm;                 // [64][AT_PITCH]
    float* W_s = sm + 4352;         // [64][128]
    for (int i = tid; i < 4096; i += 256) {
        int row = i >> 6, k = i & 63;
        At[k * AT_PITCH + row] = x[i];    // direct transpose (4-way conflict ok)
    }
    {
        const float4* wq4 = (const float4*)wq;
        const float4* wk4 = (const float4*)wk;
        for (int i = tid; i < 2048; i += 256) {
            int half = i >> 10, idx = i & 1023;
            int k = idx >> 4, c4 = (idx & 15) << 2;
            float4 v = half ? wk4[idx] : wq4[idx];
            *(float4*)&W_s[k * 128 + half * 64 + c4] = v;
        }
    }
    __syncthreads();
    qk_gemm_and_store(At, W_s, qdst, kdst, rowbase, tid);
}

// pa body: gather-attention for 64 rows of (bg, blk); att -> X_nat smem.
// q from qsrc (L2), k gathered from ksrc (L2), kv re-fetched (L1) in 2nd pass.
__device__ __forceinline__ void pa_body(
    const float* __restrict__ qsrc, const float* __restrict__ ksrc,
    const int* __restrict__ neigh, int blk, float* X_nat, int tid) {
    int w = tid >> 5, lane = tid & 31;
    int half = lane >> 4, l16 = lane & 15;
#pragma unroll
    for (int it = 0; it < 4; it++) {
        int r = w * 8 + it * 2 + half;
        int rowid = blk * 64 + r;
        int tl = rowid / N_;
        int n = rowid - tl * N_;
        const float* qb = qsrc + (size_t)tl * N_ * 64;
        const float* kb = ksrc + (size_t)tl * N_ * 64;
        float4 q = *(const float4*)&qb[(size_t)n * 64 + l16 * 4];
        float dots[K_];
        int nbs[K_];
#pragma unroll
        for (int j = 0; j < K_; j++) {
            nbs[j] = __ldg(&neigh[n * K_ + j]);
            float4 kv = __ldg((const float4*)&kb[(size_t)nbs[j] * 64 + l16 * 4]);
            float d = q.x * kv.x + q.y * kv.y + q.z * kv.z + q.w * kv.w;
            d += __shfl_xor_sync(0xffffffffu, d, 8);
            d += __shfl_xor_sync(0xffffffffu, d, 4);
            d += __shfl_xor_sync(0xffffffffu, d, 2);
            d += __shfl_xor_sync(0xffffffffu, d, 1);
            dots[j] = d;
        }
        float m = dots[0];
#pragma unroll
        for (int j = 1; j < K_; j++) m = fmaxf(m, dots[j]);
        float ssum = 0.f;
#pragma unroll
        for (int j = 0; j < K_; j++) {
            dots[j] = __expf(dots[j] - m);
            ssum += dots[j];
        }
        float inv = 1.f / ssum;
        float4 o = q;
#pragma unroll
        for (int j = 0; j < K_; j++) {
            float a = dots[j] * inv;
            float4 kv = __ldg((const float4*)&kb[(size_t)nbs[j] * 64 + l16 * 4]);
            o.x = fmaf(a, kv.x, o.x);
            o.y = fmaf(a, kv.y, o.y);
            o.z = fmaf(a, kv.z, o.z);
            o.w = fmaf(a, kv.w, o.w);
        }
        *(float4*)&X_nat[r * XN_PITCH + l16 * 4] = o;
    }
}

// x-GEMM (R8 v1 frozen loop): x = sigmoid(At' @ wd), result fn applied by caller
__device__ __forceinline__ void x_gemm(
    const float* At, const float* wd_s, ull accx[4][2], int tid) {
    int tx = tid & 31, ty = tid >> 5;
#pragma unroll
    for (int p = 0; p < 4; p++) { accx[p][0] = 0ull; accx[p][1] = 0ull; }
#pragma unroll 4
    for (int k = 0; k < 64; k++) {
        const ulonglong2* ar = (const ulonglong2*)(At + k * AT_PITCH + ty * 8);
        ulonglong2 a01 = ar[0];
        ulonglong2 a23 = ar[1];
        ull w0 = dup2(wd_s[k * 64 + tx]);
        ull w1 = dup2(wd_s[k * 64 + tx + 32]);
        fma2(accx[0][0], a01.x, w0); fma2(accx[0][1], a01.x, w1);
        fma2(accx[1][0], a01.y, w0); fma2(accx[1][1], a01.y, w1);
        fma2(accx[2][0], a23.x, w0); fma2(accx[2][1], a23.x, w1);
        fma2(accx[3][0], a23.y, w0); fma2(accx[3][1], a23.y, w1);
    }
}

// =====================================================================
// Kernel A: blocks 0-249 evo; blocks 250-1749 pass1 for sta (bg 3-5)
// =====================================================================
__global__ void __launch_bounds__(256)
kernelA(const float* __restrict__ stat,
        const float* __restrict__ thre,
        const float* __restrict__ dynn,
        const float* __restrict__ w1,
        const float* __restrict__ wq_all,
        const float* __restrict__ wk_all,
        float* __restrict__ out_nowfinal,
        float* __restrict__ out_diffs) {
    extern __shared__ float sm[];
    int tid = threadIdx.x;
    if (blockIdx.x >= 250) {
        int gblk = blockIdx.x - 250;
        int bg = 3 + gblk / 500;
        int blk = gblk - (bg - 3) * 500;
        pass1_body(stat + (size_t)blk * 4096,
                   wq_all + (size_t)(bg * 2) * 4096,
                   wk_all + (size_t)(bg * 2) * 4096,
                   g_q6[bg], g_k6[bg], (size_t)blk * 64, sm, tid);
        return;
    }
    // ---- evo (R6 logic, dynamic smem) ----
    float* w1_s = sm;                            // [8192]
    float (*now_s)[64] = (float(*)[64])(sm + 8192);
    float (*st_s)[64] = (float(*)[64])(sm + 9216);
    float* th_s = sm + 10240;                    // [16]
    for (int i = tid; i < 8192; i += 256) w1_s[i] = w1[i];
    int e = tid & 63, grp = tid >> 6;
    int row0 = blockIdx.x * 16;
#pragma unroll
    for (int i = 0; i < 4; i++) {
        int r = grp * 4 + i;
        float v = dynn[(size_t)(row0 + r) * 64 + e];
        now_s[r][e] = v;
        g_dyn[(size_t)(row0 + r) * 64 + e] = v;
    }
    __syncthreads();
    for (int t = 1; t < T_; t++) {
        size_t base = (size_t)t * RLN + row0;
        ((float4*)st_s)[tid] = ((const float4*)(stat + base * 64))[tid];
        if (tid < 16) th_s[tid] = thre[base + tid];
        __syncthreads();
        float sum[4] = {0.f, 0.f, 0.f, 0.f};
#pragma unroll 4
        for (int d = 0; d < 64; d += 4) {
            float wn0 = w1_s[(d + 0) * 64 + e];
            float wn1 = w1_s[(d + 1) * 64 + e];
            float wn2 = w1_s[(d + 2) * 64 + e];
            float wn3 = w1_s[(d + 3) * 64 + e];
            float ws0 = w1_s[(64 + d + 0) * 64 + e];
            float ws1 = w1_s[(64 + d + 1) * 64 + e];
            float ws2 = w1_s[(64 + d + 2) * 64 + e];
            float ws3 = w1_s[(64 + d + 3) * 64 + e];
#pragma unroll
            for (int i = 0; i < 4; i++) {
                int r = grp * 4 + i;
                float4 nv = *(float4*)&now_s[r][d];
                float4 sv = *(float4*)&st_s[r][d];
                sum[i] = fmaf(nv.x, wn0, sum[i]); sum[i] = fmaf(nv.y, wn1, sum[i]);
                sum[i] = fmaf(nv.z, wn2, sum[i]); sum[i] = fmaf(nv.w, wn3, sum[i]);
                sum[i] = fmaf(sv.x, ws0, sum[i]); sum[i] = fmaf(sv.y, ws1, sum[i]);
                sum[i] = fmaf(sv.z, ws2, sum[i]); sum[i] = fmaf(sv.w, ws3, sum[i]);
            }
        }
        float vals[4];
#pragma unroll
        for (int i = 0; i < 4; i++) {
            int r = grp * 4 + i;
            float th = th_s[r];
            float nv = now_s[r][e];
            float val = sigf(sum[i] * th + nv * (1.f - th));
            vals[i] = val;
            g_dyn[(base + r) * 64 + e] = val;
            out_diffs[((size_t)(t - 1) * RLN + row0 + r) * 64 + e] = val - nv;
            if (t == T_ - 1) out_nowfinal[(size_t)(row0 + r) * 64 + e] = val;
        }
        __syncthreads();
#pragma unroll
        for (int i = 0; i < 4; i++) now_s[grp * 4 + i][e] = vals[i];
        __syncthreads();
    }
}

// =====================================================================
// Kernel B: pass1 for dyn (bg 0-2). grid 1500.
// =====================================================================
__global__ void __launch_bounds__(256)
kernelB(const float* __restrict__ wq_all,
        const float* __restrict__ wk_all) {
    extern __shared__ float sm[];
    int tid = threadIdx.x;
    int bg = blockIdx.x / 500;
    int blk = blockIdx.x - bg * 500;
    pass1_body((const float*)g_dyn + (size_t)blk * 4096,
               wq_all + (size_t)(bg * 2) * 4096,
               wk_all + (size_t)(bg * 2) * 4096,
               g_q6[bg], g_k6[bg], (size_t)blk * 64, sm, tid);
}

// =====================================================================
// Kernel C: pa(s=0) + x0 = sigmoid(att@wd0) + (q1,k1) = x0@(wq1|wk1).
// grid 3000 (6 bg x 500 x 64 rows). att never touches gmem.
// smem: At[4352] | wd[4096] | X_nat[4352]
// =====================================================================
__global__ void __launch_bounds__(256)
kernelC(const int* __restrict__ n0,
        const int* __restrict__ n1,
        const int* __restrict__ n2,
        const float* __restrict__ wd_all,
        const float* __restrict__ wq_all,
        const float* __restrict__ wk_all) {
    extern __shared__ float sm[];
    float* At = sm;                  // [64][AT_PITCH]
    float* region = sm + 4352;       // wd[4096] then W_s[8192]
    float* wd_s = region;            // [64][64]
    float* X_nat = sm + 8448;        // [64][XN_PITCH]
    int tid = threadIdx.x;
    int bg = blockIdx.x / 500;
    int blk = blockIdx.x - bg * 500;
    int gi3 = bg % 3;
    const int* neigh = (gi3 == 0) ? n0 : (gi3 == 1) ? n1 : n2;

    // phase 1: pa -> X_nat ; wd0 -> wd_s
    pa_body(g_q6[bg], g_k6[bg], neigh, blk, X_nat, tid);
    {
        const float4* wd4 = (const float4*)(wd_all + (size_t)(bg * 2) * 4096);
        for (int i = tid; i < 1024; i += 256) ((float4*)wd_s)[i] = wd4[i];
    }
    __syncthreads();
    // phase 2: transpose X_nat -> At
    for (int i = tid; i < 4096; i += 256) {
        int k = i >> 6, row = i & 63;
        At[k * AT_PITCH + row] = X_nat[row * XN_PITCH + k];
    }
    __syncthreads();
    // phase 3: x-GEMM
    ull accx[4][2];
    x_gemm(At, wd_s, accx, tid);
    __syncthreads();
    // phase 4: xT -> At ; wq1/wk1 -> region (overwrites wd)
    int tx = tid & 31, ty = tid >> 5;
#pragma unroll
    for (int p = 0; p < 4; p++) {
        int r0 = ty * 8 + 2 * p;
        *(float2*)&At[tx * AT_PITCH + r0] =
            make_float2(sigf(lo32(accx[p][0])), sigf(hi32(accx[p][0])));
        *(float2*)&At[(tx + 32) * AT_PITCH + r0] =
            make_float2(sigf(lo32(accx[p][1])), sigf(hi32(accx[p][1])));
    }
    {
        const float4* wq4 = (const float4*)(wq_all + (size_t)(bg * 2 + 1) * 4096);
        const float4* wk4 = (const float4*)(wk_all + (size_t)(bg * 2 + 1) * 4096);
        for (int i = tid; i < 2048; i += 256) {
            int half = i >> 10, idx = i & 1023;
            int k = idx >> 4, c4 = (idx & 15) << 2;
            float4 v = half ? wk4[idx] : wq4[idx];
            *(float4*)&region[k * 128 + half * 64 + c4] = v;
        }
    }
    __syncthreads();
    // phase 5: q/k GEMM -> stage-1 buffers
    qk_gemm_and_store(At, region, g_q6b[bg], g_k6b[bg], (size_t)blk * 64, tid);
}

// =====================================================================
// Kernel D: pa(s=1) + x1 = sigmoid(att@wd1) -> g_x6. grid 3000.
// =====================================================================
__global__ void __launch_bounds__(256)
kernelD(const int* __restrict__ n0,
        const int* __restrict__ n1,
        const int* __restrict__ n2,
        const float* __restrict__ wd_all) {
    extern __shared__ float sm[];
    float* At = sm;                  // [64][AT_PITCH]
    float* wd_s = sm + 4352;         // [64][64]
    float* X_nat = sm + 8448;        // [64][XN_PITCH]
    int tid = threadIdx.x;
    int bg = blockIdx.x / 500;
    int blk = blockIdx.x - bg * 500;
    int gi3 = bg % 3;
    const int* neigh = (gi3 == 0) ? n0 : (gi3 == 1) ? n1 : n2;

    pa_body(g_q6b[bg], g_k6b[bg], neigh, blk, X_nat, tid);
    {
        const float4* wd4 = (const float4*)(wd_all + (size_t)(bg * 2 + 1) * 4096);
        for (int i = tid; i < 1024; i += 256) ((float4*)wd_s)[i] = wd4[i];
    }
    __syncthreads();
    for (int i = tid; i < 4096; i += 256) {
        int k = i >> 6, row = i & 63;
        At[k * AT_PITCH + row] = X_nat[row * XN_PITCH + k];
    }
    __syncthreads();
    ull accx[4][2];
    x_gemm(At, wd_s, accx, tid);

    int tx = tid & 31, ty = tid >> 5;
    float* xdst = g_x6[bg] + (size_t)blk * 4096;
#pragma unroll
    for (int p = 0; p < 4; p++) {
        int r0 = ty * 8 + 2 * p;
        xdst[(size_t)r0 * 64 + tx]            = sigf(lo32(accx[p][0]));
        xdst[(size_t)(r0 + 1) * 64 + tx]      = sigf(hi32(accx[p][0]));
        xdst[(size_t)r0 * 64 + tx + 32]       = sigf(lo32(accx[p][1]));
        xdst[(size_t)(r0 + 1) * 64 + tx + 32] = sigf(hi32(accx[p][1]));
    }
}

// =====================================================================
// LSTM over L with fused mix: warp per (t,n). grid 500 x 256. (R7)
// =====================================================================
__global__ void lstm_kernel(const float* __restrict__ convw,
                            const float* __restrict__ convb,
                            const float* __restrict__ wmix) {
    __shared__ float cw[4 * 129];
    __shared__ float cb[4];
    __shared__ float wm_s[2 * 192];
    int tid = threadIdx.x;
    for (int i = tid; i < 516; i += 256) cw[i] = convw[i];
    if (tid < 4) cb[tid] = convb[tid];
    if (tid < 128) {
        wm_s[tid] = wmix[tid];
        wm_s[tid + 128] = wmix[tid + 128];
        wm_s[tid + 256] = wmix[tid + 256];
    }
    __syncthreads();
    int gw = blockIdx.x * 8 + (tid >> 5);
    int lane = tid & 31;
    int t = gw / N_, n = gw % N_;
    int b = lane >> 4;
    int dl = (lane & 15) * 4;
    int dbase = b * 64 + dl;
    float wreg[4][4], wh[4], bb[4];
#pragma unroll
    for (int i = 0; i < 4; i++) {
#pragma unroll
        for (int q = 0; q < 4; q++) wreg[i][q] = cw[i * 129 + dbase + q];
        wh[i] = cw[i * 129 + 128];
        bb[i] = cb[i];
    }
    const float* wm = wm_s + b * 192;
    float4 m0 = *(const float4*)&wm[dl];
    float4 m1 = *(const float4*)&wm[64 + dl];
    float4 m2 = *(const float4*)&wm[128 + dl];

    float h = 0.f, c = 0.f;
    for (int l = 0; l < L_; l++) {
        size_t off = (((size_t)t * L_ + l) * N_ + n) * 64 + dl;
        float4 x0 = *(const float4*)&g_x6[b * 3 + 0][off];
        float4 x1 = *(const float4*)&g_x6[b * 3 + 1][off];
        float4 x2 = *(const float4*)&g_x6[b * 3 + 2][off];
        float4 xin;
        xin.x = sigf(x0.x * m0.x + x1.x * m1.x + x2.x * m2.x);
        xin.y = sigf(x0.y * m0.y + x1.y * m1.y + x2.y * m2.y);
        xin.z = sigf(x0.z * m0.z + x1.z * m1.z + x2.z * m2.z);
        xin.w = sigf(x0.w * m0.w + x1.w * m1.w + x2.w * m2.w);
        float s[4];
#pragma unroll
        for (int i = 0; i < 4; i++) {
            s[i] = xin.x * wreg[i][0] + xin.y * wreg[i][1] +
                   xin.z * wreg[i][2] + xin.w * wreg[i][3];
#pragma unroll
            for (int o = 16; o; o >>= 1)
                s[i] += __shfl_xor_sync(0xffffffffu, s[i], o);
        }
        float gi = sigf(s[0] + h * wh[0] + bb[0]);
        float gf = sigf(s[1] + h * wh[1] + bb[1]);
        float go = sigf(s[2] + h * wh[2] + bb[2]);
        float gg = tanhf(s[3] + h * wh[3] + bb[3]);
        c = gf * c + gi * gg;
        h = go * tanhf(c);
    }
    if (lane == 0) g_h[t * N_ + n] = h;
}

// =====================================================================
// final projection: grid T_, block 512
// =====================================================================
__global__ void final_kernel(const float* __restrict__ finw,
                             const float* __restrict__ finb,
                             float* __restrict__ out) {
    __shared__ float hs[500];
    int t = blockIdx.x, tid = threadIdx.x;
    if (tid < 500) hs[tid] = g_h[t * N_ + tid];
    __syncthreads();
    if (tid < 500) {
        float acc = finb[tid];
        const float4* wr = (const float4*)(finw + (size_t)tid * 500);
#pragma unroll 5
        for (int m4 = 0; m4 < 125; m4++) {
            float4 wv = wr[m4];
            acc = fmaf(hs[m4 * 4 + 0], wv.x, acc);
            acc = fmaf(hs[m4 * 4 + 1], wv.y, acc);
            acc = fmaf(hs[m4 * 4 + 2], wv.z, acc);
            acc = fmaf(hs[m4 * 4 + 3], wv.w, acc);
        }
        out[t * N_ + tid] = sigf(acc);
    }
}

// ---------------- launcher ----------------
extern "C" void kernel_launch(void* const* d_in, const int* in_sizes, int n_in,
                              void* d_out, int out_size) {
    const float* stat = (const float*)d_in[0];
    const float* thre = (const float*)d_in[1];
    const float* dynn = (const float*)d_in[2];
    const int* npoi = (const int*)d_in[3];
    const int* nroad = (const int*)d_in[4];
    const int* nrec = (const int*)d_in[5];
    const float* w1 = (const float*)d_in[6];
    const float* wq = (const float*)d_in[7];
    const float* wk = (const float*)d_in[8];
    const float* wdm = (const float*)d_in[9];
    const float* wmix = (const float*)d_in[10];
    const float* convw = (const float*)d_in[11];
    const float* convb = (const float*)d_in[12];
    const float* finw = (const float*)d_in[13];
    const float* finb = (const float*)d_in[14];

    float* out = (float*)d_out;
    float* out_scores = out;                          // (T,N)       4000
    float* out_nowfinal = out + T_ * N_;              // (L,N,D)     256000
    float* out_diffs = out + T_ * N_ + L_ * N_ * D_;  // (T-1,L,N,D) 1792000

    cudaFuncSetAttribute(kernelA,
                         cudaFuncAttributeMaxDynamicSharedMemorySize, P1_SMEM);
    cudaFuncSetAttribute(kernelB,
                         cudaFuncAttributeMaxDynamicSharedMemorySize, P1_SMEM);
    cudaFuncSetAttribute(kernelC,
                         cudaFuncAttributeMaxDynamicSharedMemorySize, PC_SMEM);
    cudaFuncSetAttribute(kernelD,
                         cudaFuncAttributeMaxDynamicSharedMemorySize, PC_SMEM);

    kernelA<<<1750, 256, P1_SMEM>>>(stat, thre, dynn, w1, wq, wk,
                                    out_nowfinal, out_diffs);   // evo + pass1_sta
    kernelB<<<1500, 256, P1_SMEM>>>(wq, wk);                    // pass1_dyn
    kernelC<<<3000, 256, PC_SMEM>>>(npoi, nroad, nrec, wdm, wq, wk);
    kernelD<<<3000, 256, PC_SMEM>>>(npoi, nroad, nrec, wdm);
    lstm_kernel<<<500, 256>>>(convw, convb, wmix);
    final_kernel<<<T_, 512>>>(finw, finb, out_scores);
}

// round 14
// speedup vs baseline: 1.1390x; 1.0168x over previous
#include <cuda_runtime.h>
#include <cuda_bf16.h>
#include <cstdint>

// Problem constants
#define T_ 8
#define L_ 8
#define N_ 500
#define D_ 64
#define K_ 12
#define S_ 2
#define RLN (L_*N_)          // 4000
#define R_ (T_*L_*N_)        // 32000 rows of (t,l,n)
#define ELEMS (R_*D_)        // 2048000

typedef unsigned long long ull;

// ---------------- scratch buffers (no allocation allowed) ----------------
__device__ float g_dyn[ELEMS];          // all_dyn (T,L,N,D)
__device__ float g_q6[6][ELEMS];        // stage-0 q
__device__ float g_k6[6][ELEMS];        // stage-0 k
__device__ float g_q6b[6][ELEMS];       // stage-1 q
__device__ float g_k6b[6][ELEMS];       // stage-1 k
__device__ float g_x6[6][ELEMS];        // final attention output
__device__ float g_h[T_*N_];            // LSTM h_last

__device__ __forceinline__ float sigf(float x) {
    return 1.f / (1.f + __expf(-x));
}

__device__ __forceinline__ void fma2(ull& acc, ull a, ull b) {
    asm("fma.rn.f32x2 %0, %1, %2, %0;" : "+l"(acc) : "l"(a), "l"(b));
}
__device__ __forceinline__ float lo32(ull v) { return __uint_as_float((unsigned)v); }
__device__ __forceinline__ float hi32(ull v) { return __uint_as_float((unsigned)(v >> 32)); }
__device__ __forceinline__ ull dup2(float a) {
    ull r; unsigned u = __float_as_uint(a);
    asm("mov.b64 %0, {%1, %1};" : "=l"(r) : "r"(u));
    return r;
}

// =====================================================================
// shared device bodies
// =====================================================================
#define AT_PITCH 68
#define XN_PITCH 68
// pass1 smem: At[64*68]=4352 + W[64*128]=8192 -> 12544 floats
#define P1_SMEM (12544 * 4)     // 50176
// kernelC/D smem: At 4352 + wd 4096 + X_nat 4352 -> 12800 floats
#define PC_SMEM (12800 * 4)     // 51200

// q/k GEMM inner (R4 frozen loop, W pitch 128). At ready, W_s ready.
__device__ __forceinline__ void qk_gemm_and_store(
    const float* At, const float* W_s, float* qdst, float* kdst,
    size_t rowbase, int tid) {
    int tx = tid & 31, ty = tid >> 5;
    ull acc[8][2];
#pragma unroll
    for (int r = 0; r < 8; r++) { acc[r][0] = 0ull; acc[r][1] = 0ull; }
#pragma unroll 4
    for (int k = 0; k < 64; k++) {
        float4 a0 = *(const float4*)&At[k * AT_PITCH + ty * 8];
        float4 a1 = *(const float4*)&At[k * AT_PITCH + ty * 8 + 4];
        const ull* wrow = (const ull*)&W_s[k * 128];
        ull wq2 = wrow[tx];
        ull wk2 = wrow[tx + 32];
        ull ad[8];
        ad[0] = dup2(a0.x); ad[1] = dup2(a0.y); ad[2] = dup2(a0.z); ad[3] = dup2(a0.w);
        ad[4] = dup2(a1.x); ad[5] = dup2(a1.y); ad[6] = dup2(a1.z); ad[7] = dup2(a1.w);
#pragma unroll
        for (int r = 0; r < 8; r++) {
            fma2(acc[r][0], ad[r], wq2);
            fma2(acc[r][1], ad[r], wk2);
        }
    }
#pragma unroll
    for (int r = 0; r < 8; r++) {
        size_t ro = (rowbase + r) * 64 + 2 * tx;
        *(float2*)&qdst[ro] = make_float2(lo32(acc[r][0]), hi32(acc[r][0]));
        *(float2*)&kdst[ro] = make_float2(lo32(acc[r][1]), hi32(acc[r][1]));
    }
}

// pass1 body: direct transposed load of X + W load + GEMM
__device__ __forceinline__ void pass1_body(
    const float* __restrict__ x, const float* __restrict__ wq,
    const float* __restrict__ wk, float* qdst, float* kdst,
    size_t rowbase, float* sm, int tid) {
    float* At = sm;                 // [64][AT_PITCH]
    float* W_s = sm + 4352;         // [64][128]
    for (int i = tid; i < 4096; i += 256) {
        int row = i >> 6, k = i & 63;
        At[k * AT_PITCH + row] = x[i];    // direct transpose
    }
    {
        const float4* wq4 = (const float4*)wq;
        const float4* wk4 = (const float4*)wk;
        for (int i = tid; i < 2048; i += 256) {
            int half = i >> 10, idx = i & 1023;
            int k = idx >> 4, c4 = (idx & 15) << 2;
            float4 v = half ? wk4[idx] : wq4[idx];
            *(float4*)&W_s[k * 128 + half * 64 + c4] = v;
        }
    }
    __syncthreads();
    qk_gemm_and_store(At, W_s, qdst, kdst, rowbase, tid);
}

// pa body: gather-attention for 64 rows of (bg, blk); att -> X_nat smem.
__device__ __forceinline__ void pa_body(
    const float* __restrict__ qsrc, const float* __restrict__ ksrc,
    const int* __restrict__ neigh, int blk, float* X_nat, int tid) {
    int w = tid >> 5, lane = tid & 31;
    int half = lane >> 4, l16 = lane & 15;
#pragma unroll
    for (int it = 0; it < 4; it++) {
        int r = w * 8 + it * 2 + half;
        int rowid = blk * 64 + r;
        int tl = rowid / N_;
        int n = rowid - tl * N_;
        const float* qb = qsrc + (size_t)tl * N_ * 64;
        const float* kb = ksrc + (size_t)tl * N_ * 64;
        float4 q = *(const float4*)&qb[(size_t)n * 64 + l16 * 4];
        float dots[K_];
        int nbs[K_];
#pragma unroll
        for (int j = 0; j < K_; j++) {
            nbs[j] = __ldg(&neigh[n * K_ + j]);
            float4 kv = __ldg((const float4*)&kb[(size_t)nbs[j] * 64 + l16 * 4]);
            float d = q.x * kv.x + q.y * kv.y + q.z * kv.z + q.w * kv.w;
            d += __shfl_xor_sync(0xffffffffu, d, 8);
            d += __shfl_xor_sync(0xffffffffu, d, 4);
            d += __shfl_xor_sync(0xffffffffu, d, 2);
            d += __shfl_xor_sync(0xffffffffu, d, 1);
            dots[j] = d;
        }
        float m = dots[0];
#pragma unroll
        for (int j = 1; j < K_; j++) m = fmaxf(m, dots[j]);
        float ssum = 0.f;
#pragma unroll
        for (int j = 0; j < K_; j++) {
            dots[j] = __expf(dots[j] - m);
            ssum += dots[j];
        }
        float inv = 1.f / ssum;
        float4 o = q;
#pragma unroll
        for (int j = 0; j < K_; j++) {
            float a = dots[j] * inv;
            float4 kv = __ldg((const float4*)&kb[(size_t)nbs[j] * 64 + l16 * 4]);
            o.x = fmaf(a, kv.x, o.x);
            o.y = fmaf(a, kv.y, o.y);
            o.z = fmaf(a, kv.z, o.z);
            o.w = fmaf(a, kv.w, o.w);
        }
        *(float4*)&X_nat[r * XN_PITCH + l16 * 4] = o;
    }
}

// x-GEMM (R8 v1 frozen loop)
__device__ __forceinline__ void x_gemm(
    const float* At, const float* wd_s, ull accx[4][2], int tid) {
    int tx = tid & 31, ty = tid >> 5;
#pragma unroll
    for (int p = 0; p < 4; p++) { accx[p][0] = 0ull; accx[p][1] = 0ull; }
#pragma unroll 4
    for (int k = 0; k < 64; k++) {
        const ulonglong2* ar = (const ulonglong2*)(At + k * AT_PITCH + ty * 8);
        ulonglong2 a01 = ar[0];
        ulonglong2 a23 = ar[1];
        ull w0 = dup2(wd_s[k * 64 + tx]);
        ull w1 = dup2(wd_s[k * 64 + tx + 32]);
        fma2(accx[0][0], a01.x, w0); fma2(accx[0][1], a01.x, w1);
        fma2(accx[1][0], a01.y, w0); fma2(accx[1][1], a01.y, w1);
        fma2(accx[2][0], a23.x, w0); fma2(accx[2][1], a23.x, w1);
        fma2(accx[3][0], a23.y, w0); fma2(accx[3][1], a23.y, w1);
    }
}

// =====================================================================
// Kernel A: blocks 0-249 evo; blocks 250-1749 pass1 for sta (bg 3-5)
// =====================================================================
__global__ void __launch_bounds__(256)
kernelA(const float* __restrict__ stat,
        const float* __restrict__ thre,
        const float* __restrict__ dynn,
        const float* __restrict__ w1,
        const float* __restrict__ wq_all,
        const float* __restrict__ wk_all,
        float* __restrict__ out_nowfinal,
        float* __restrict__ out_diffs) {
    extern __shared__ float sm[];
    int tid = threadIdx.x;
    if (blockIdx.x >= 250) {
        int gblk = blockIdx.x - 250;
        int bg = 3 + gblk / 500;
        int blk = gblk - (bg - 3) * 500;
        pass1_body(stat + (size_t)blk * 4096,
                   wq_all + (size_t)(bg * 2) * 4096,
                   wk_all + (size_t)(bg * 2) * 4096,
                   g_q6[bg], g_k6[bg], (size_t)blk * 64, sm, tid);
        return;
    }
    // ---- evo ----
    float* w1_s = sm;                            // [8192]
    float (*now_s)[64] = (float(*)[64])(sm + 8192);
    float (*st_s)[64] = (float(*)[64])(sm + 9216);
    float* th_s = sm + 10240;                    // [16]
    for (int i = tid; i < 8192; i += 256) w1_s[i] = w1[i];
    int e = tid & 63, grp = tid >> 6;
    int row0 = blockIdx.x * 16;
#pragma unroll
    for (int i = 0; i < 4; i++) {
        int r = grp * 4 + i;
        float v = dynn[(size_t)(row0 + r) * 64 + e];
        now_s[r][e] = v;
        g_dyn[(size_t)(row0 + r) * 64 + e] = v;
    }
    __syncthreads();
    for (int t = 1; t < T_; t++) {
        size_t base = (size_t)t * RLN + row0;
        ((float4*)st_s)[tid] = ((const float4*)(stat + base * 64))[tid];
        if (tid < 16) th_s[tid] = thre[base + tid];
        __syncthreads();
        float sum[4] = {0.f, 0.f, 0.f, 0.f};
#pragma unroll 4
        for (int d = 0; d < 64; d += 4) {
            float wn0 = w1_s[(d + 0) * 64 + e];
            float wn1 = w1_s[(d + 1) * 64 + e];
            float wn2 = w1_s[(d + 2) * 64 + e];
            float wn3 = w1_s[(d + 3) * 64 + e];
            float ws0 = w1_s[(64 + d + 0) * 64 + e];
            float ws1 = w1_s[(64 + d + 1) * 64 + e];
            float ws2 = w1_s[(64 + d + 2) * 64 + e];
            float ws3 = w1_s[(64 + d + 3) * 64 + e];
#pragma unroll
            for (int i = 0; i < 4; i++) {
                int r = grp * 4 + i;
                float4 nv = *(float4*)&now_s[r][d];
                float4 sv = *(float4*)&st_s[r][d];
                sum[i] = fmaf(nv.x, wn0, sum[i]); sum[i] = fmaf(nv.y, wn1, sum[i]);
                sum[i] = fmaf(nv.z, wn2, sum[i]); sum[i] = fmaf(nv.w, wn3, sum[i]);
                sum[i] = fmaf(sv.x, ws0, sum[i]); sum[i] = fmaf(sv.y, ws1, sum[i]);
                sum[i] = fmaf(sv.z, ws2, sum[i]); sum[i] = fmaf(sv.w, ws3, sum[i]);
            }
        }
        float vals[4];
#pragma unroll
        for (int i = 0; i < 4; i++) {
            int r = grp * 4 + i;
            float th = th_s[r];
            float nv = now_s[r][e];
            float val = sigf(sum[i] * th + nv * (1.f - th));
            vals[i] = val;
            g_dyn[(base + r) * 64 + e] = val;
            out_diffs[((size_t)(t - 1) * RLN + row0 + r) * 64 + e] = val - nv;
            if (t == T_ - 1) out_nowfinal[(size_t)(row0 + r) * 64 + e] = val;
        }
        __syncthreads();
#pragma unroll
        for (int i = 0; i < 4; i++) now_s[grp * 4 + i][e] = vals[i];
        __syncthreads();
    }
}

// =====================================================================
// Kernel B: pass1 for dyn (bg 0-2). grid 1500.
// =====================================================================
__global__ void __launch_bounds__(256)
kernelB(const float* __restrict__ wq_all,
        const float* __restrict__ wk_all) {
    extern __shared__ float sm[];
    int tid = threadIdx.x;
    int bg = blockIdx.x / 500;
    int blk = blockIdx.x - bg * 500;
    pass1_body((const float*)g_dyn + (size_t)blk * 4096,
               wq_all + (size_t)(bg * 2) * 4096,
               wk_all + (size_t)(bg * 2) * 4096,
               g_q6[bg], g_k6[bg], (size_t)blk * 64, sm, tid);
}

// =====================================================================
// Kernel C: pa(s=0) + x0 = sigmoid(att@wd0) + (q1,k1) = x0@(wq1|wk1).
// grid 3000. __launch_bounds__(256,4): cap regs at 64 -> 4 blocks/SM.
// =====================================================================
__global__ void __launch_bounds__(256, 4)
kernelC(const int* __restrict__ n0,
        const int* __restrict__ n1,
        const int* __restrict__ n2,
        const float* __restrict__ wd_all,
        const float* __restrict__ wq_all,
        const float* __restrict__ wk_all) {
    extern __shared__ float sm[];
    float* At = sm;                  // [64][AT_PITCH]
    float* region = sm + 4352;       // wd[4096] then W_s[8192]
    float* wd_s = region;            // [64][64]
    float* X_nat = sm + 8448;        // [64][XN_PITCH]
    int tid = threadIdx.x;
    int bg = blockIdx.x / 500;
    int blk = blockIdx.x - bg * 500;
    int gi3 = bg % 3;
    const int* neigh = (gi3 == 0) ? n0 : (gi3 == 1) ? n1 : n2;

    pa_body(g_q6[bg], g_k6[bg], neigh, blk, X_nat, tid);
    {
        const float4* wd4 = (const float4*)(wd_all + (size_t)(bg * 2) * 4096);
        for (int i = tid; i < 1024; i += 256) ((float4*)wd_s)[i] = wd4[i];
    }
    __syncthreads();
    for (int i = tid; i < 4096; i += 256) {
        int k = i >> 6, row = i & 63;
        At[k * AT_PITCH + row] = X_nat[row * XN_PITCH + k];
    }
    __syncthreads();
    ull accx[4][2];
    x_gemm(At, wd_s, accx, tid);
    __syncthreads();
    int tx = tid & 31, ty = tid >> 5;
#pragma unroll
    for (int p = 0; p < 4; p++) {
        int r0 = ty * 8 + 2 * p;
        *(float2*)&At[tx * AT_PITCH + r0] =
            make_float2(sigf(lo32(accx[p][0])), sigf(hi32(accx[p][0])));
        *(float2*)&At[(tx + 32) * AT_PITCH + r0] =
            make_float2(sigf(lo32(accx[p][1])), sigf(hi32(accx[p][1])));
    }
    {
        const float4* wq4 = (const float4*)(wq_all + (size_t)(bg * 2 + 1) * 4096);
        const float4* wk4 = (const float4*)(wk_all + (size_t)(bg * 2 + 1) * 4096);
        for (int i = tid; i < 2048; i += 256) {
            int half = i >> 10, idx = i & 1023;
            int k = idx >> 4, c4 = (idx & 15) << 2;
            float4 v = half ? wk4[idx] : wq4[idx];
            *(float4*)&region[k * 128 + half * 64 + c4] = v;
        }
    }
    __syncthreads();
    qk_gemm_and_store(At, region, g_q6b[bg], g_k6b[bg], (size_t)blk * 64, tid);
}

// =====================================================================
// Kernel D: pa(s=1) + x1 = sigmoid(att@wd1) -> g_x6. grid 3000.
// =====================================================================
__global__ void __launch_bounds__(256, 4)
kernelD(const int* __restrict__ n0,
        const int* __restrict__ n1,
        const int* __restrict__ n2,
        const float* __restrict__ wd_all) {
    extern __shared__ float sm[];
    float* At = sm;                  // [64][AT_PITCH]
    float* wd_s = sm + 4352;         // [64][64]
    float* X_nat = sm + 8448;        // [64][XN_PITCH]
    int tid = threadIdx.x;
    int bg = blockIdx.x / 500;
    int blk = blockIdx.x - bg * 500;
    int gi3 = bg % 3;
    const int* neigh = (gi3 == 0) ? n0 : (gi3 == 1) ? n1 : n2;

    pa_body(g_q6b[bg], g_k6b[bg], neigh, blk, X_nat, tid);
    {
        const float4* wd4 = (const float4*)(wd_all + (size_t)(bg * 2 + 1) * 4096);
        for (int i = tid; i < 1024; i += 256) ((float4*)wd_s)[i] = wd4[i];
    }
    __syncthreads();
    for (int i = tid; i < 4096; i += 256) {
        int k = i >> 6, row = i & 63;
        At[k * AT_PITCH + row] = X_nat[row * XN_PITCH + k];
    }
    __syncthreads();
    ull accx[4][2];
    x_gemm(At, wd_s, accx, tid);

    int tx = tid & 31, ty = tid >> 5;
    float* xdst = g_x6[bg] + (size_t)blk * 4096;
#pragma unroll
    for (int p = 0; p < 4; p++) {
        int r0 = ty * 8 + 2 * p;
        xdst[(size_t)r0 * 64 + tx]            = sigf(lo32(accx[p][0]));
        xdst[(size_t)(r0 + 1) * 64 + tx]      = sigf(hi32(accx[p][0]));
        xdst[(size_t)r0 * 64 + tx + 32]       = sigf(lo32(accx[p][1]));
        xdst[(size_t)(r0 + 1) * 64 + tx + 32] = sigf(hi32(accx[p][1]));
    }
}

// =====================================================================
// LSTM over L with fused mix: warp per (t,n). grid 500 x 256. (R7)
// =====================================================================
__global__ void lstm_kernel(const float* __restrict__ convw,
                            const float* __restrict__ convb,
                            const float* __restrict__ wmix) {
    __shared__ float cw[4 * 129];
    __shared__ float cb[4];
    __shared__ float wm_s[2 * 192];
    int tid = threadIdx.x;
    for (int i = tid; i < 516; i += 256) cw[i] = convw[i];
    if (tid < 4) cb[tid] = convb[tid];
    if (tid < 128) {
        wm_s[tid] = wmix[tid];
        wm_s[tid + 128] = wmix[tid + 128];
        wm_s[tid + 256] = wmix[tid + 256];
    }
    __syncthreads();
    int gw = blockIdx.x * 8 + (tid >> 5);
    int lane = tid & 31;
    int t = gw / N_, n = gw % N_;
    int b = lane >> 4;
    int dl = (lane & 15) * 4;
    int dbase = b * 64 + dl;
    float wreg[4][4], wh[4], bb[4];
#pragma unroll
    for (int i = 0; i < 4; i++) {
#pragma unroll
        for (int q = 0; q < 4; q++) wreg[i][q] = cw[i * 129 + dbase + q];
        wh[i] = cw[i * 129 + 128];
        bb[i] = cb[i];
    }
    const float* wm = wm_s + b * 192;
    float4 m0 = *(const float4*)&wm[dl];
    float4 m1 = *(const float4*)&wm[64 + dl];
    float4 m2 = *(const float4*)&wm[128 + dl];

    float h = 0.f, c = 0.f;
    for (int l = 0; l < L_; l++) {
        size_t off = (((size_t)t * L_ + l) * N_ + n) * 64 + dl;
        float4 x0 = *(const float4*)&g_x6[b * 3 + 0][off];
        float4 x1 = *(const float4*)&g_x6[b * 3 + 1][off];
        float4 x2 = *(const float4*)&g_x6[b * 3 + 2][off];
        float4 xin;
        xin.x = sigf(x0.x * m0.x + x1.x * m1.x + x2.x * m2.x);
        xin.y = sigf(x0.y * m0.y + x1.y * m1.y + x2.y * m2.y);
        xin.z = sigf(x0.z * m0.z + x1.z * m1.z + x2.z * m2.z);
        xin.w = sigf(x0.w * m0.w + x1.w * m1.w + x2.w * m2.w);
        float s[4];
#pragma unroll
        for (int i = 0; i < 4; i++) {
            s[i] = xin.x * wreg[i][0] + xin.y * wreg[i][1] +
                   xin.z * wreg[i][2] + xin.w * wreg[i][3];
#pragma unroll
            for (int o = 16; o; o >>= 1)
                s[i] += __shfl_xor_sync(0xffffffffu, s[i], o);
        }
        float gi = sigf(s[0] + h * wh[0] + bb[0]);
        float gf = sigf(s[1] + h * wh[1] + bb[1]);
        float go = sigf(s[2] + h * wh[2] + bb[2]);
        float gg = tanhf(s[3] + h * wh[3] + bb[3]);
        c = gf * c + gi * gg;
        h = go * tanhf(c);
    }
    if (lane == 0) g_h[t * N_ + n] = h;
}

// =====================================================================
// final projection: grid T_, block 512
// =====================================================================
__global__ void final_kernel(const float* __restrict__ finw,
                             const float* __restrict__ finb,
                             float* __restrict__ out) {
    __shared__ float hs[500];
    int t = blockIdx.x, tid = threadIdx.x;
    if (tid < 500) hs[tid] = g_h[t * N_ + tid];
    __syncthreads();
    if (tid < 500) {
        float acc = finb[tid];
        const float4* wr = (const float4*)(finw + (size_t)tid * 500);
#pragma unroll 5
        for (int m4 = 0; m4 < 125; m4++) {
            float4 wv = wr[m4];
            acc = fmaf(hs[m4 * 4 + 0], wv.x, acc);
            acc = fmaf(hs[m4 * 4 + 1], wv.y, acc);
            acc = fmaf(hs[m4 * 4 + 2], wv.z, acc);
            acc = fmaf(hs[m4 * 4 + 3], wv.w, acc);
        }
        out[t * N_ + tid] = sigf(acc);
    }
}

// ---------------- launcher ----------------
extern "C" void kernel_launch(void* const* d_in, const int* in_sizes, int n_in,
                              void* d_out, int out_size) {
    const float* stat = (const float*)d_in[0];
    const float* thre = (const float*)d_in[1];
    const float* dynn = (const float*)d_in[2];
    const int* npoi = (const int*)d_in[3];
    const int* nroad = (const int*)d_in[4];
    const int* nrec = (const int*)d_in[5];
    const float* w1 = (const float*)d_in[6];
    const float* wq = (const float*)d_in[7];
    const float* wk = (const float*)d_in[8];
    const float* wdm = (const float*)d_in[9];
    const float* wmix = (const float*)d_in[10];
    const float* convw = (const float*)d_in[11];
    const float* convb = (const float*)d_in[12];
    const float* finw = (const float*)d_in[13];
    const float* finb = (const float*)d_in[14];

    float* out = (float*)d_out;
    float* out_scores = out;                          // (T,N)       4000
    float* out_nowfinal = out + T_ * N_;              // (L,N,D)     256000
    float* out_diffs = out + T_ * N_ + L_ * N_ * D_;  // (T-1,L,N,D) 1792000

    cudaFuncSetAttribute(kernelA,
                         cudaFuncAttributeMaxDynamicSharedMemorySize, P1_SMEM);
    cudaFuncSetAttribute(kernelB,
                         cudaFuncAttributeMaxDynamicSharedMemorySize, P1_SMEM);
    cudaFuncSetAttribute(kernelC,
                         cudaFuncAttributeMaxDynamicSharedMemorySize, PC_SMEM);
    cudaFuncSetAttribute(kernelD,
                         cudaFuncAttributeMaxDynamicSharedMemorySize, PC_SMEM);

    kernelA<<<1750, 256, P1_SMEM>>>(stat, thre, dynn, w1, wq, wk,
                                    out_nowfinal, out_diffs);   // evo + pass1_sta
    kernelB<<<1500, 256, P1_SMEM>>>(wq, wk);                    // pass1_dyn
    kernelC<<<3000, 256, PC_SMEM>>>(npoi, nroad, nrec, wdm, wq, wk);
    kernelD<<<3000, 256, PC_SMEM>>>(npoi, nroad, nrec, wdm);
    lstm_kernel<<<500, 256>>>(convw, convb, wmix);
    final_kernel<<<T_, 512>>>(finw, finb, out_scores);
}

// round 15
// speedup vs baseline: 1.2452x; 1.0932x over previous
#include <cuda_runtime.h>
#include <cuda_bf16.h>
#include <cstdint>

// Problem constants
#define T_ 8
#define L_ 8
#define N_ 500
#define D_ 64
#define K_ 12
#define S_ 2
#define RLN (L_*N_)          // 4000
#define R_ (T_*L_*N_)        // 32000 rows of (t,l,n)
#define ELEMS (R_*D_)        // 2048000

typedef unsigned long long ull;

// ---------------- scratch buffers (no allocation allowed) ----------------
__device__ float g_dyn[ELEMS];          // all_dyn (T,L,N,D)
__device__ float g_q6[6][ELEMS];        // stage-0 q
__device__ float g_k6[6][ELEMS];        // stage-0 k
__device__ float g_q6b[6][ELEMS];       // stage-1 q
__device__ float g_k6b[6][ELEMS];       // stage-1 k
__device__ float g_x6[6][ELEMS];        // final attention output
__device__ float g_h[T_*N_];            // LSTM h_last

__device__ __forceinline__ float sigf(float x) {
    return 1.f / (1.f + __expf(-x));
}

__device__ __forceinline__ void fma2(ull& acc, ull a, ull b) {
    asm("fma.rn.f32x2 %0, %1, %2, %0;" : "+l"(acc) : "l"(a), "l"(b));
}
__device__ __forceinline__ float lo32(ull v) { return __uint_as_float((unsigned)v); }
__device__ __forceinline__ float hi32(ull v) { return __uint_as_float((unsigned)(v >> 32)); }
__device__ __forceinline__ ull dup2(float a) {
    ull r; unsigned u = __float_as_uint(a);
    asm("mov.b64 %0, {%1, %1};" : "=l"(r) : "r"(u));
    return r;
}

// =====================================================================
// shared device bodies
// =====================================================================
#define AT_PITCH 68
#define XN_PITCH 68
// pass1 smem: At[64*68]=4352 + W[64*128]=8192 -> 12544 floats
#define P1_SMEM (12544 * 4)     // 50176
// kernelC/D smem: At 4352 + wd 4096 + X_nat 4352 -> 12800 floats
#define PC_SMEM (12800 * 4)     // 51200

// q/k GEMM inner (R4 frozen loop, W pitch 128). At ready, W_s ready.
__device__ __forceinline__ void qk_gemm_and_store(
    const float* At, const float* W_s, float* qdst, float* kdst,
    size_t rowbase, int tid) {
    int tx = tid & 31, ty = tid >> 5;
    ull acc[8][2];
#pragma unroll
    for (int r = 0; r < 8; r++) { acc[r][0] = 0ull; acc[r][1] = 0ull; }
#pragma unroll 4
    for (int k = 0; k < 64; k++) {
        float4 a0 = *(const float4*)&At[k * AT_PITCH + ty * 8];
        float4 a1 = *(const float4*)&At[k * AT_PITCH + ty * 8 + 4];
        const ull* wrow = (const ull*)&W_s[k * 128];
        ull wq2 = wrow[tx];
        ull wk2 = wrow[tx + 32];
        ull ad[8];
        ad[0] = dup2(a0.x); ad[1] = dup2(a0.y); ad[2] = dup2(a0.z); ad[3] = dup2(a0.w);
        ad[4] = dup2(a1.x); ad[5] = dup2(a1.y); ad[6] = dup2(a1.z); ad[7] = dup2(a1.w);
#pragma unroll
        for (int r = 0; r < 8; r++) {
            fma2(acc[r][0], ad[r], wq2);
            fma2(acc[r][1], ad[r], wk2);
        }
    }
#pragma unroll
    for (int r = 0; r < 8; r++) {
        size_t ro = (rowbase + r) * 64 + 2 * tx;
        *(float2*)&qdst[ro] = make_float2(lo32(acc[r][0]), hi32(acc[r][0]));
        *(float2*)&kdst[ro] = make_float2(lo32(acc[r][1]), hi32(acc[r][1]));
    }
}

// pass1 body: direct transposed load of X + W load + GEMM
__device__ __forceinline__ void pass1_body(
    const float* __restrict__ x, const float* __restrict__ wq,
    const float* __restrict__ wk, float* qdst, float* kdst,
    size_t rowbase, float* sm, int tid) {
    float* At = sm;                 // [64][AT_PITCH]
    float* W_s = sm + 4352;         // [64][128]
    for (int i = tid; i < 4096; i += 256) {
        int row = i >> 6, k = i & 63;
        At[k * AT_PITCH + row] = x[i];    // direct transpose
    }
    {
        const float4* wq4 = (const float4*)wq;
        const float4* wk4 = (const float4*)wk;
        for (int i = tid; i < 2048; i += 256) {
            int half = i >> 10, idx = i & 1023;
            int k = idx >> 4, c4 = (idx & 15) << 2;
            float4 v = half ? wk4[idx] : wq4[idx];
            *(float4*)&W_s[k * 128 + half * 64 + c4] = v;
        }
    }
    __syncthreads();
    qk_gemm_and_store(At, W_s, qdst, kdst, rowbase, tid);
}

// pa body, ONE-PASS online softmax: att -> X_nat smem.
// Single gather per neighbor; running max/sum with rescaled partial o.
__device__ __forceinline__ void pa_body(
    const float* __restrict__ qsrc, const float* __restrict__ ksrc,
    const int* __restrict__ neigh, int blk, float* X_nat, int tid) {
    int w = tid >> 5, lane = tid & 31;
    int half = lane >> 4, l16 = lane & 15;
#pragma unroll
    for (int it = 0; it < 4; it++) {
        int r = w * 8 + it * 2 + half;
        int rowid = blk * 64 + r;
        int tl = rowid / N_;
        int n = rowid - tl * N_;
        const float* qb = qsrc + (size_t)tl * N_ * 64;
        const float* kb = ksrc + (size_t)tl * N_ * 64;
        float4 q = *(const float4*)&qb[(size_t)n * 64 + l16 * 4];

        float m_run = -1e30f, ssum = 0.f;
        float4 o = make_float4(0.f, 0.f, 0.f, 0.f);
#pragma unroll
        for (int j = 0; j < K_; j++) {
            int nb = __ldg(&neigh[n * K_ + j]);
            float4 kv = __ldg((const float4*)&kb[(size_t)nb * 64 + l16 * 4]);
            float d = q.x * kv.x + q.y * kv.y + q.z * kv.z + q.w * kv.w;
            d += __shfl_xor_sync(0xffffffffu, d, 8);
            d += __shfl_xor_sync(0xffffffffu, d, 4);
            d += __shfl_xor_sync(0xffffffffu, d, 2);
            d += __shfl_xor_sync(0xffffffffu, d, 1);
            float wj;
            if (d > m_run) {
                float sc = __expf(m_run - d);    // 0 on first iter
                ssum *= sc;
                o.x *= sc; o.y *= sc; o.z *= sc; o.w *= sc;
                m_run = d;
                wj = 1.f;
            } else {
                wj = __expf(d - m_run);
            }
            ssum += wj;
            o.x = fmaf(wj, kv.x, o.x);
            o.y = fmaf(wj, kv.y, o.y);
            o.z = fmaf(wj, kv.z, o.z);
            o.w = fmaf(wj, kv.w, o.w);
        }
        float inv = 1.f / ssum;
        float4 res;
        res.x = fmaf(o.x, inv, q.x);
        res.y = fmaf(o.y, inv, q.y);
        res.z = fmaf(o.z, inv, q.z);
        res.w = fmaf(o.w, inv, q.w);
        *(float4*)&X_nat[r * XN_PITCH + l16 * 4] = res;
    }
}

// x-GEMM (R8 v1 frozen loop)
__device__ __forceinline__ void x_gemm(
    const float* At, const float* wd_s, ull accx[4][2], int tid) {
    int tx = tid & 31, ty = tid >> 5;
#pragma unroll
    for (int p = 0; p < 4; p++) { accx[p][0] = 0ull; accx[p][1] = 0ull; }
#pragma unroll 4
    for (int k = 0; k < 64; k++) {
        const ulonglong2* ar = (const ulonglong2*)(At + k * AT_PITCH + ty * 8);
        ulonglong2 a01 = ar[0];
        ulonglong2 a23 = ar[1];
        ull w0 = dup2(wd_s[k * 64 + tx]);
        ull w1 = dup2(wd_s[k * 64 + tx + 32]);
        fma2(accx[0][0], a01.x, w0); fma2(accx[0][1], a01.x, w1);
        fma2(accx[1][0], a01.y, w0); fma2(accx[1][1], a01.y, w1);
        fma2(accx[2][0], a23.x, w0); fma2(accx[2][1], a23.x, w1);
        fma2(accx[3][0], a23.y, w0); fma2(accx[3][1], a23.y, w1);
    }
}

// =====================================================================
// Kernel A: blocks 0-249 evo; blocks 250-1749 pass1 for sta (bg 3-5)
// =====================================================================
__global__ void __launch_bounds__(256)
kernelA(const float* __restrict__ stat,
        const float* __restrict__ thre,
        const float* __restrict__ dynn,
        const float* __restrict__ w1,
        const float* __restrict__ wq_all,
        const float* __restrict__ wk_all,
        float* __restrict__ out_nowfinal,
        float* __restrict__ out_diffs) {
    extern __shared__ float sm[];
    int tid = threadIdx.x;
    if (blockIdx.x >= 250) {
        int gblk = blockIdx.x - 250;
        int bg = 3 + gblk / 500;
        int blk = gblk - (bg - 3) * 500;
        pass1_body(stat + (size_t)blk * 4096,
                   wq_all + (size_t)(bg * 2) * 4096,
                   wk_all + (size_t)(bg * 2) * 4096,
                   g_q6[bg], g_k6[bg], (size_t)blk * 64, sm, tid);
        return;
    }
    // ---- evo ----
    float* w1_s = sm;                            // [8192]
    float (*now_s)[64] = (float(*)[64])(sm + 8192);
    float (*st_s)[64] = (float(*)[64])(sm + 9216);
    float* th_s = sm + 10240;                    // [16]
    for (int i = tid; i < 8192; i += 256) w1_s[i] = w1[i];
    int e = tid & 63, grp = tid >> 6;
    int row0 = blockIdx.x * 16;
#pragma unroll
    for (int i = 0; i < 4; i++) {
        int r = grp * 4 + i;
        float v = dynn[(size_t)(row0 + r) * 64 + e];
        now_s[r][e] = v;
        g_dyn[(size_t)(row0 + r) * 64 + e] = v;
    }
    __syncthreads();
    for (int t = 1; t < T_; t++) {
        size_t base = (size_t)t * RLN + row0;
        ((float4*)st_s)[tid] = ((const float4*)(stat + base * 64))[tid];
        if (tid < 16) th_s[tid] = thre[base + tid];
        __syncthreads();
        float sum[4] = {0.f, 0.f, 0.f, 0.f};
#pragma unroll 4
        for (int d = 0; d < 64; d += 4) {
            float wn0 = w1_s[(d + 0) * 64 + e];
            float wn1 = w1_s[(d + 1) * 64 + e];
            float wn2 = w1_s[(d + 2) * 64 + e];
            float wn3 = w1_s[(d + 3) * 64 + e];
            float ws0 = w1_s[(64 + d + 0) * 64 + e];
            float ws1 = w1_s[(64 + d + 1) * 64 + e];
            float ws2 = w1_s[(64 + d + 2) * 64 + e];
            float ws3 = w1_s[(64 + d + 3) * 64 + e];
#pragma unroll
            for (int i = 0; i < 4; i++) {
                int r = grp * 4 + i;
                float4 nv = *(float4*)&now_s[r][d];
                float4 sv = *(float4*)&st_s[r][d];
                sum[i] = fmaf(nv.x, wn0, sum[i]); sum[i] = fmaf(nv.y, wn1, sum[i]);
                sum[i] = fmaf(nv.z, wn2, sum[i]); sum[i] = fmaf(nv.w, wn3, sum[i]);
                sum[i] = fmaf(sv.x, ws0, sum[i]); sum[i] = fmaf(sv.y, ws1, sum[i]);
                sum[i] = fmaf(sv.z, ws2, sum[i]); sum[i] = fmaf(sv.w, ws3, sum[i]);
            }
        }
        float vals[4];
#pragma unroll
        for (int i = 0; i < 4; i++) {
            int r = grp * 4 + i;
            float th = th_s[r];
            float nv = now_s[r][e];
            float val = sigf(sum[i] * th + nv * (1.f - th));
            vals[i] = val;
            g_dyn[(base + r) * 64 + e] = val;
            out_diffs[((size_t)(t - 1) * RLN + row0 + r) * 64 + e] = val - nv;
            if (t == T_ - 1) out_nowfinal[(size_t)(row0 + r) * 64 + e] = val;
        }
        __syncthreads();
#pragma unroll
        for (int i = 0; i < 4; i++) now_s[grp * 4 + i][e] = vals[i];
        __syncthreads();
    }
}

// =====================================================================
// Kernel B: pass1 for dyn (bg 0-2). grid 1500.
// =====================================================================
__global__ void __launch_bounds__(256)
kernelB(const float* __restrict__ wq_all,
        const float* __restrict__ wk_all) {
    extern __shared__ float sm[];
    int tid = threadIdx.x;
    int bg = blockIdx.x / 500;
    int blk = blockIdx.x - bg * 500;
    pass1_body((const float*)g_dyn + (size_t)blk * 4096,
               wq_all + (size_t)(bg * 2) * 4096,
               wk_all + (size_t)(bg * 2) * 4096,
               g_q6[bg], g_k6[bg], (size_t)blk * 64, sm, tid);
}

// =====================================================================
// Kernel C: pa(s=0) + x0 = sigmoid(att@wd0) + (q1,k1) = x0@(wq1|wk1).
// grid 3000. __launch_bounds__(256,4).
// =====================================================================
__global__ void __launch_bounds__(256, 4)
kernelC(const int* __restrict__ n0,
        const int* __restrict__ n1,
        const int* __restrict__ n2,
        const float* __restrict__ wd_all,
        const float* __restrict__ wq_all,
        const float* __restrict__ wk_all) {
    extern __shared__ float sm[];
    float* At = sm;                  // [64][AT_PITCH]
    float* region = sm + 4352;       // wd[4096] then W_s[8192]
    float* wd_s = region;            // [64][64]
    float* X_nat = sm + 8448;        // [64][XN_PITCH]
    int tid = threadIdx.x;
    int bg = blockIdx.x / 500;
    int blk = blockIdx.x - bg * 500;
    int gi3 = bg % 3;
    const int* neigh = (gi3 == 0) ? n0 : (gi3 == 1) ? n1 : n2;

    pa_body(g_q6[bg], g_k6[bg], neigh, blk, X_nat, tid);
    {
        const float4* wd4 = (const float4*)(wd_all + (size_t)(bg * 2) * 4096);
        for (int i = tid; i < 1024; i += 256) ((float4*)wd_s)[i] = wd4[i];
    }
    __syncthreads();
    for (int i = tid; i < 4096; i += 256) {
        int k = i >> 6, row = i & 63;
        At[k * AT_PITCH + row] = X_nat[row * XN_PITCH + k];
    }
    __syncthreads();
    ull accx[4][2];
    x_gemm(At, wd_s, accx, tid);
    __syncthreads();
    int tx = tid & 31, ty = tid >> 5;
#pragma unroll
    for (int p = 0; p < 4; p++) {
        int r0 = ty * 8 + 2 * p;
        *(float2*)&At[tx * AT_PITCH + r0] =
            make_float2(sigf(lo32(accx[p][0])), sigf(hi32(accx[p][0])));
        *(float2*)&At[(tx + 32) * AT_PITCH + r0] =
            make_float2(sigf(lo32(accx[p][1])), sigf(hi32(accx[p][1])));
    }
    {
        const float4* wq4 = (const float4*)(wq_all + (size_t)(bg * 2 + 1) * 4096);
        const float4* wk4 = (const float4*)(wk_all + (size_t)(bg * 2 + 1) * 4096);
        for (int i = tid; i < 2048; i += 256) {
            int half = i >> 10, idx = i & 1023;
            int k = idx >> 4, c4 = (idx & 15) << 2;
            float4 v = half ? wk4[idx] : wq4[idx];
            *(float4*)&region[k * 128 + half * 64 + c4] = v;
        }
    }
    __syncthreads();
    qk_gemm_and_store(At, region, g_q6b[bg], g_k6b[bg], (size_t)blk * 64, tid);
}

// =====================================================================
// Kernel D: pa(s=1) + x1 = sigmoid(att@wd1) -> g_x6. grid 3000.
// =====================================================================
__global__ void __launch_bounds__(256, 4)
kernelD(const int* __restrict__ n0,
        const int* __restrict__ n1,
        const int* __restrict__ n2,
        const float* __restrict__ wd_all) {
    extern __shared__ float sm[];
    float* At = sm;                  // [64][AT_PITCH]
    float* wd_s = sm + 4352;         // [64][64]
    float* X_nat = sm + 8448;        // [64][XN_PITCH]
    int tid = threadIdx.x;
    int bg = blockIdx.x / 500;
    int blk = blockIdx.x - bg * 500;
    int gi3 = bg % 3;
    const int* neigh = (gi3 == 0) ? n0 : (gi3 == 1) ? n1 : n2;

    pa_body(g_q6b[bg], g_k6b[bg], neigh, blk, X_nat, tid);
    {
        const float4* wd4 = (const float4*)(wd_all + (size_t)(bg * 2 + 1) * 4096);
        for (int i = tid; i < 1024; i += 256) ((float4*)wd_s)[i] = wd4[i];
    }
    __syncthreads();
    for (int i = tid; i < 4096; i += 256) {
        int k = i >> 6, row = i & 63;
        At[k * AT_PITCH + row] = X_nat[row * XN_PITCH + k];
    }
    __syncthreads();
    ull accx[4][2];
    x_gemm(At, wd_s, accx, tid);

    int tx = tid & 31, ty = tid >> 5;
    float* xdst = g_x6[bg] + (size_t)blk * 4096;
#pragma unroll
    for (int p = 0; p < 4; p++) {
        int r0 = ty * 8 + 2 * p;
        xdst[(size_t)r0 * 64 + tx]            = sigf(lo32(accx[p][0]));
        xdst[(size_t)(r0 + 1) * 64 + tx]      = sigf(hi32(accx[p][0]));
        xdst[(size_t)r0 * 64 + tx + 32]       = sigf(lo32(accx[p][1]));
        xdst[(size_t)(r0 + 1) * 64 + tx + 32] = sigf(hi32(accx[p][1]));
    }
}

// =====================================================================
// LSTM over L with fused mix: warp per (t,n). grid 500 x 256. (R7)
// =====================================================================
__global__ void lstm_kernel(const float* __restrict__ convw,
                            const float* __restrict__ convb,
                            const float* __restrict__ wmix) {
    __shared__ float cw[4 * 129];
    __shared__ float cb[4];
    __shared__ float wm_s[2 * 192];
    int tid = threadIdx.x;
    for (int i = tid; i < 516; i += 256) cw[i] = convw[i];
    if (tid < 4) cb[tid] = convb[tid];
    if (tid < 128) {
        wm_s[tid] = wmix[tid];
        wm_s[tid + 128] = wmix[tid + 128];
        wm_s[tid + 256] = wmix[tid + 256];
    }
    __syncthreads();
    int gw = blockIdx.x * 8 + (tid >> 5);
    int lane = tid & 31;
    int t = gw / N_, n = gw % N_;
    int b = lane >> 4;
    int dl = (lane & 15) * 4;
    int dbase = b * 64 + dl;
    float wreg[4][4], wh[4], bb[4];
#pragma unroll
    for (int i = 0; i < 4; i++) {
#pragma unroll
        for (int q = 0; q < 4; q++) wreg[i][q] = cw[i * 129 + dbase + q];
        wh[i] = cw[i * 129 + 128];
        bb[i] = cb[i];
    }
    const float* wm = wm_s + b * 192;
    float4 m0 = *(const float4*)&wm[dl];
    float4 m1 = *(const float4*)&wm[64 + dl];
    float4 m2 = *(const float4*)&wm[128 + dl];

    float h = 0.f, c = 0.f;
    for (int l = 0; l < L_; l++) {
        size_t off = (((size_t)t * L_ + l) * N_ + n) * 64 + dl;
        float4 x0 = *(const float4*)&g_x6[b * 3 + 0][off];
        float4 x1 = *(const float4*)&g_x6[b * 3 + 1][off];
        float4 x2 = *(const float4*)&g_x6[b * 3 + 2][off];
        float4 xin;
        xin.x = sigf(x0.x * m0.x + x1.x * m1.x + x2.x * m2.x);
        xin.y = sigf(x0.y * m0.y + x1.y * m1.y + x2.y * m2.y);
        xin.z = sigf(x0.z * m0.z + x1.z * m1.z + x2.z * m2.z);
        xin.w = sigf(x0.w * m0.w + x1.w * m1.w + x2.w * m2.w);
        float s[4];
#pragma unroll
        for (int i = 0; i < 4; i++) {
            s[i] = xin.x * wreg[i][0] + xin.y * wreg[i][1] +
                   xin.z * wreg[i][2] + xin.w * wreg[i][3];
#pragma unroll
            for (int o = 16; o; o >>= 1)
                s[i] += __shfl_xor_sync(0xffffffffu, s[i], o);
        }
        float gi = sigf(s[0] + h * wh[0] + bb[0]);
        float gf = sigf(s[1] + h * wh[1] + bb[1]);
        float go = sigf(s[2] + h * wh[2] + bb[2]);
        float gg = tanhf(s[3] + h * wh[3] + bb[3]);
        c = gf * c + gi * gg;
        h = go * tanhf(c);
    }
    if (lane == 0) g_h[t * N_ + n] = h;
}

// =====================================================================
// final projection: grid T_, block 512
// =====================================================================
__global__ void final_kernel(const float* __restrict__ finw,
                             const float* __restrict__ finb,
                             float* __restrict__ out) {
    __shared__ float hs[500];
    int t = blockIdx.x, tid = threadIdx.x;
    if (tid < 500) hs[tid] = g_h[t * N_ + tid];
    __syncthreads();
    if (tid < 500) {
        float acc = finb[tid];
        const float4* wr = (const float4*)(finw + (size_t)tid * 500);
#pragma unroll 5
        for (int m4 = 0; m4 < 125; m4++) {
            float4 wv = wr[m4];
            acc = fmaf(hs[m4 * 4 + 0], wv.x, acc);
            acc = fmaf(hs[m4 * 4 + 1], wv.y, acc);
            acc = fmaf(hs[m4 * 4 + 2], wv.z, acc);
            acc = fmaf(hs[m4 * 4 + 3], wv.w, acc);
        }
        out[t * N_ + tid] = sigf(acc);
    }
}

// ---------------- launcher ----------------
extern "C" void kernel_launch(void* const* d_in, const int* in_sizes, int n_in,
                              void* d_out, int out_size) {
    const float* stat = (const float*)d_in[0];
    const float* thre = (const float*)d_in[1];
    const float* dynn = (const float*)d_in[2];
    const int* npoi = (const int*)d_in[3];
    const int* nroad = (const int*)d_in[4];
    const int* nrec = (const int*)d_in[5];
    const float* w1 = (const float*)d_in[6];
    const float* wq = (const float*)d_in[7];
    const float* wk = (const float*)d_in[8];
    const float* wdm = (const float*)d_in[9];
    const float* wmix = (const float*)d_in[10];
    const float* convw = (const float*)d_in[11];
    const float* convb = (const float*)d_in[12];
    const float* finw = (const float*)d_in[13];
    const float* finb = (const float*)d_in[14];

    float* out = (float*)d_out;
    float* out_scores = out;                          // (T,N)       4000
    float* out_nowfinal = out + T_ * N_;              // (L,N,D)     256000
    float* out_diffs = out + T_ * N_ + L_ * N_ * D_;  // (T-1,L,N,D) 1792000

    cudaFuncSetAttribute(kernelA,
                         cudaFuncAttributeMaxDynamicSharedMemorySize, P1_SMEM);
    cudaFuncSetAttribute(kernelB,
                         cudaFuncAttributeMaxDynamicSharedMemorySize, P1_SMEM);
    cudaFuncSetAttribute(kernelC,
                         cudaFuncAttributeMaxDynamicSharedMemorySize, PC_SMEM);
    cudaFuncSetAttribute(kernelD,
                         cudaFuncAttributeMaxDynamicSharedMemorySize, PC_SMEM);

    kernelA<<<1750, 256, P1_SMEM>>>(stat, thre, dynn, w1, wq, wk,
                                    out_nowfinal, out_diffs);   // evo + pass1_sta
    kernelB<<<1500, 256, P1_SMEM>>>(wq, wk);                    // pass1_dyn
    kernelC<<<3000, 256, PC_SMEM>>>(npoi, nroad, nrec, wdm, wq, wk);
    kernelD<<<3000, 256, PC_SMEM>>>(npoi, nroad, nrec, wdm);
    lstm_kernel<<<500, 256>>>(convw, convb, wmix);
    final_kernel<<<T_, 512>>>(finw, finb, out_scores);
}

// round 16
// speedup vs baseline: 1.3134x; 1.0548x over previous
#include <cuda_runtime.h>
#include <cuda_bf16.h>
#include <cstdint>

// Problem constants
#define T_ 8
#define L_ 8
#define N_ 500
#define D_ 64
#define K_ 12
#define S_ 2
#define RLN (L_*N_)          // 4000
#define R_ (T_*L_*N_)        // 32000 rows of (t,l,n)
#define ELEMS (R_*D_)        // 2048000

typedef unsigned long long ull;

// ---------------- scratch buffers (no allocation allowed) ----------------
__device__ float g_dyn[ELEMS];          // all_dyn (T,L,N,D)
__device__ float g_q6[6][ELEMS];        // stage-0 q
__device__ float g_k6[6][ELEMS];        // stage-0 k
__device__ float g_q6b[6][ELEMS];       // stage-1 q
__device__ float g_k6b[6][ELEMS];       // stage-1 k
__device__ float g_x6[6][ELEMS];        // final attention output
__device__ float g_h[T_*N_];            // LSTM h_last

__device__ __forceinline__ float sigf(float x) {
    return 1.f / (1.f + __expf(-x));
}

__device__ __forceinline__ void fma2(ull& acc, ull a, ull b) {
    asm("fma.rn.f32x2 %0, %1, %2, %0;" : "+l"(acc) : "l"(a), "l"(b));
}
__device__ __forceinline__ float lo32(ull v) { return __uint_as_float((unsigned)v); }
__device__ __forceinline__ float hi32(ull v) { return __uint_as_float((unsigned)(v >> 32)); }
__device__ __forceinline__ ull dup2(float a) {
    ull r; unsigned u = __float_as_uint(a);
    asm("mov.b64 %0, {%1, %1};" : "=l"(r) : "r"(u));
    return r;
}

// =====================================================================
// shared device bodies
// =====================================================================
#define AT_PITCH 68
// pass1/kernelC smem: At[64*68]=4352 + W[64*128]=8192 -> 12544 floats
#define P1_SMEM (12544 * 4)     // 50176
// kernelD smem: At 4352 + wd 4096 -> 8448 floats
#define PD_SMEM (8448 * 4)      // 33792

// q/k GEMM inner (R4 frozen loop, W pitch 128). At ready, W_s ready.
__device__ __forceinline__ void qk_gemm_and_store(
    const float* At, const float* W_s, float* qdst, float* kdst,
    size_t rowbase, int tid) {
    int tx = tid & 31, ty = tid >> 5;
    ull acc[8][2];
#pragma unroll
    for (int r = 0; r < 8; r++) { acc[r][0] = 0ull; acc[r][1] = 0ull; }
#pragma unroll 4
    for (int k = 0; k < 64; k++) {
        float4 a0 = *(const float4*)&At[k * AT_PITCH + ty * 8];
        float4 a1 = *(const float4*)&At[k * AT_PITCH + ty * 8 + 4];
        const ull* wrow = (const ull*)&W_s[k * 128];
        ull wq2 = wrow[tx];
        ull wk2 = wrow[tx + 32];
        ull ad[8];
        ad[0] = dup2(a0.x); ad[1] = dup2(a0.y); ad[2] = dup2(a0.z); ad[3] = dup2(a0.w);
        ad[4] = dup2(a1.x); ad[5] = dup2(a1.y); ad[6] = dup2(a1.z); ad[7] = dup2(a1.w);
#pragma unroll
        for (int r = 0; r < 8; r++) {
            fma2(acc[r][0], ad[r], wq2);
            fma2(acc[r][1], ad[r], wk2);
        }
    }
#pragma unroll
    for (int r = 0; r < 8; r++) {
        size_t ro = (rowbase + r) * 64 + 2 * tx;
        *(float2*)&qdst[ro] = make_float2(lo32(acc[r][0]), hi32(acc[r][0]));
        *(float2*)&kdst[ro] = make_float2(lo32(acc[r][1]), hi32(acc[r][1]));
    }
}

// pass1 body: direct transposed load of X + W load + GEMM
__device__ __forceinline__ void pass1_body(
    const float* __restrict__ x, const float* __restrict__ wq,
    const float* __restrict__ wk, float* qdst, float* kdst,
    size_t rowbase, float* sm, int tid) {
    float* At = sm;                 // [64][AT_PITCH]
    float* W_s = sm + 4352;         // [64][128]
    for (int i = tid; i < 4096; i += 256) {
        int row = i >> 6, k = i & 63;
        At[k * AT_PITCH + row] = x[i];    // direct transpose
    }
    {
        const float4* wq4 = (const float4*)wq;
        const float4* wk4 = (const float4*)wk;
        for (int i = tid; i < 2048; i += 256) {
            int half = i >> 10, idx = i & 1023;
            int k = idx >> 4, c4 = (idx & 15) << 2;
            float4 v = half ? wk4[idx] : wq4[idx];
            *(float4*)&W_s[k * 128 + half * 64 + c4] = v;
        }
    }
    __syncthreads();
    qk_gemm_and_store(At, W_s, qdst, kdst, rowbase, tid);
}

// pa body, one-pass NO-MAX softmax; writes att DIRECTLY TRANSPOSED to At.
// Valid because |dot| is bounded (inputs sigmoid/N(0,1), weights ~0.05):
// exp cannot overflow fp32; softmax is shift-invariant.
__device__ __forceinline__ void pa_body(
    const float* __restrict__ qsrc, const float* __restrict__ ksrc,
    const int* __restrict__ neigh, int blk, float* At, int tid) {
    int w = tid >> 5, lane = tid & 31;
    int half = lane >> 4, l16 = lane & 15;
#pragma unroll
    for (int it = 0; it < 4; it++) {
        int r = w * 8 + it * 2 + half;
        int rowid = blk * 64 + r;
        int tl = rowid / N_;
        int n = rowid - tl * N_;
        const float* qb = qsrc + (size_t)tl * N_ * 64;
        const float* kb = ksrc + (size_t)tl * N_ * 64;
        float4 q = *(const float4*)&qb[(size_t)n * 64 + l16 * 4];

        float ssum = 0.f;
        float4 o = make_float4(0.f, 0.f, 0.f, 0.f);
#pragma unroll
        for (int j = 0; j < K_; j++) {
            int nb = __ldg(&neigh[n * K_ + j]);
            float4 kv = __ldg((const float4*)&kb[(size_t)nb * 64 + l16 * 4]);
            float d = q.x * kv.x + q.y * kv.y + q.z * kv.z + q.w * kv.w;
            d += __shfl_xor_sync(0xffffffffu, d, 8);
            d += __shfl_xor_sync(0xffffffffu, d, 4);
            d += __shfl_xor_sync(0xffffffffu, d, 2);
            d += __shfl_xor_sync(0xffffffffu, d, 1);
            float wj = __expf(d);
            ssum += wj;
            o.x = fmaf(wj, kv.x, o.x);
            o.y = fmaf(wj, kv.y, o.y);
            o.z = fmaf(wj, kv.z, o.z);
            o.w = fmaf(wj, kv.w, o.w);
        }
        float inv = 1.f / ssum;
        // direct transposed store: At[k][row]
        At[(l16 * 4 + 0) * AT_PITCH + r] = fmaf(o.x, inv, q.x);
        At[(l16 * 4 + 1) * AT_PITCH + r] = fmaf(o.y, inv, q.y);
        At[(l16 * 4 + 2) * AT_PITCH + r] = fmaf(o.z, inv, q.z);
        At[(l16 * 4 + 3) * AT_PITCH + r] = fmaf(o.w, inv, q.w);
    }
}

// x-GEMM (R8 v1 frozen loop)
__device__ __forceinline__ void x_gemm(
    const float* At, const float* wd_s, ull accx[4][2], int tid) {
    int tx = tid & 31, ty = tid >> 5;
#pragma unroll
    for (int p = 0; p < 4; p++) { accx[p][0] = 0ull; accx[p][1] = 0ull; }
#pragma unroll 4
    for (int k = 0; k < 64; k++) {
        const ulonglong2* ar = (const ulonglong2*)(At + k * AT_PITCH + ty * 8);
        ulonglong2 a01 = ar[0];
        ulonglong2 a23 = ar[1];
        ull w0 = dup2(wd_s[k * 64 + tx]);
        ull w1 = dup2(wd_s[k * 64 + tx + 32]);
        fma2(accx[0][0], a01.x, w0); fma2(accx[0][1], a01.x, w1);
        fma2(accx[1][0], a01.y, w0); fma2(accx[1][1], a01.y, w1);
        fma2(accx[2][0], a23.x, w0); fma2(accx[2][1], a23.x, w1);
        fma2(accx[3][0], a23.y, w0); fma2(accx[3][1], a23.y, w1);
    }
}

// =====================================================================
// Kernel A: blocks 0-249 evo; blocks 250-1749 pass1 for sta (bg 3-5)
// =====================================================================
__global__ void __launch_bounds__(256)
kernelA(const float* __restrict__ stat,
        const float* __restrict__ thre,
        const float* __restrict__ dynn,
        const float* __restrict__ w1,
        const float* __restrict__ wq_all,
        const float* __restrict__ wk_all,
        float* __restrict__ out_nowfinal,
        float* __restrict__ out_diffs) {
    extern __shared__ float sm[];
    int tid = threadIdx.x;
    if (blockIdx.x >= 250) {
        int gblk = blockIdx.x - 250;
        int bg = 3 + gblk / 500;
        int blk = gblk - (bg - 3) * 500;
        pass1_body(stat + (size_t)blk * 4096,
                   wq_all + (size_t)(bg * 2) * 4096,
                   wk_all + (size_t)(bg * 2) * 4096,
                   g_q6[bg], g_k6[bg], (size_t)blk * 64, sm, tid);
        return;
    }
    // ---- evo ----
    float* w1_s = sm;                            // [8192]
    float (*now_s)[64] = (float(*)[64])(sm + 8192);
    float (*st_s)[64] = (float(*)[64])(sm + 9216);
    float* th_s = sm + 10240;                    // [16]
    for (int i = tid; i < 8192; i += 256) w1_s[i] = w1[i];
    int e = tid & 63, grp = tid >> 6;
    int row0 = blockIdx.x * 16;
#pragma unroll
    for (int i = 0; i < 4; i++) {
        int r = grp * 4 + i;
        float v = dynn[(size_t)(row0 + r) * 64 + e];
        now_s[r][e] = v;
        g_dyn[(size_t)(row0 + r) * 64 + e] = v;
    }
    __syncthreads();
    for (int t = 1; t < T_; t++) {
        size_t base = (size_t)t * RLN + row0;
        ((float4*)st_s)[tid] = ((const float4*)(stat + base * 64))[tid];
        if (tid < 16) th_s[tid] = thre[base + tid];
        __syncthreads();
        float sum[4] = {0.f, 0.f, 0.f, 0.f};
#pragma unroll 4
        for (int d = 0; d < 64; d += 4) {
            float wn0 = w1_s[(d + 0) * 64 + e];
            float wn1 = w1_s[(d + 1) * 64 + e];
            float wn2 = w1_s[(d + 2) * 64 + e];
            float wn3 = w1_s[(d + 3) * 64 + e];
            float ws0 = w1_s[(64 + d + 0) * 64 + e];
            float ws1 = w1_s[(64 + d + 1) * 64 + e];
            float ws2 = w1_s[(64 + d + 2) * 64 + e];
            float ws3 = w1_s[(64 + d + 3) * 64 + e];
#pragma unroll
            for (int i = 0; i < 4; i++) {
                int r = grp * 4 + i;
                float4 nv = *(float4*)&now_s[r][d];
                float4 sv = *(float4*)&st_s[r][d];
                sum[i] = fmaf(nv.x, wn0, sum[i]); sum[i] = fmaf(nv.y, wn1, sum[i]);
                sum[i] = fmaf(nv.z, wn2, sum[i]); sum[i] = fmaf(nv.w, wn3, sum[i]);
                sum[i] = fmaf(sv.x, ws0, sum[i]); sum[i] = fmaf(sv.y, ws1, sum[i]);
                sum[i] = fmaf(sv.z, ws2, sum[i]); sum[i] = fmaf(sv.w, ws3, sum[i]);
            }
        }
        float vals[4];
#pragma unroll
        for (int i = 0; i < 4; i++) {
            int r = grp * 4 + i;
            float th = th_s[r];
            float nv = now_s[r][e];
            float val = sigf(sum[i] * th + nv * (1.f - th));
            vals[i] = val;
            g_dyn[(base + r) * 64 + e] = val;
            out_diffs[((size_t)(t - 1) * RLN + row0 + r) * 64 + e] = val - nv;
            if (t == T_ - 1) out_nowfinal[(size_t)(row0 + r) * 64 + e] = val;
        }
        __syncthreads();
#pragma unroll
        for (int i = 0; i < 4; i++) now_s[grp * 4 + i][e] = vals[i];
        __syncthreads();
    }
}

// =====================================================================
// Kernel B: pass1 for dyn (bg 0-2). grid 1500.
// =====================================================================
__global__ void __launch_bounds__(256)
kernelB(const float* __restrict__ wq_all,
        const float* __restrict__ wk_all) {
    extern __shared__ float sm[];
    int tid = threadIdx.x;
    int bg = blockIdx.x / 500;
    int blk = blockIdx.x - bg * 500;
    pass1_body((const float*)g_dyn + (size_t)blk * 4096,
               wq_all + (size_t)(bg * 2) * 4096,
               wk_all + (size_t)(bg * 2) * 4096,
               g_q6[bg], g_k6[bg], (size_t)blk * 64, sm, tid);
}

// =====================================================================
// Kernel C: pa(s=0)->At + x0 = sigmoid(att@wd0) + (q1,k1) = x0@(wq1|wk1).
// grid 3000. __launch_bounds__(256,4). smem: At[4352] | region[8192]
// =====================================================================
__global__ void __launch_bounds__(256, 4)
kernelC(const int* __restrict__ n0,
        const int* __restrict__ n1,
        const int* __restrict__ n2,
        const float* __restrict__ wd_all,
        const float* __restrict__ wq_all,
        const float* __restrict__ wk_all) {
    extern __shared__ float sm[];
    float* At = sm;                  // [64][AT_PITCH]
    float* region = sm + 4352;       // wd[4096] then W_s[8192]
    float* wd_s = region;            // [64][64]
    int tid = threadIdx.x;
    int bg = blockIdx.x / 500;
    int blk = blockIdx.x - bg * 500;
    int gi3 = bg % 3;
    const int* neigh = (gi3 == 0) ? n0 : (gi3 == 1) ? n1 : n2;

    pa_body(g_q6[bg], g_k6[bg], neigh, blk, At, tid);   // att -> At (transposed)
    {
        const float4* wd4 = (const float4*)(wd_all + (size_t)(bg * 2) * 4096);
        for (int i = tid; i < 1024; i += 256) ((float4*)wd_s)[i] = wd4[i];
    }
    __syncthreads();
    ull accx[4][2];
    x_gemm(At, wd_s, accx, tid);
    __syncthreads();
    int tx = tid & 31, ty = tid >> 5;
#pragma unroll
    for (int p = 0; p < 4; p++) {
        int r0 = ty * 8 + 2 * p;
        *(float2*)&At[tx * AT_PITCH + r0] =
            make_float2(sigf(lo32(accx[p][0])), sigf(hi32(accx[p][0])));
        *(float2*)&At[(tx + 32) * AT_PITCH + r0] =
            make_float2(sigf(lo32(accx[p][1])), sigf(hi32(accx[p][1])));
    }
    {
        const float4* wq4 = (const float4*)(wq_all + (size_t)(bg * 2 + 1) * 4096);
        const float4* wk4 = (const float4*)(wk_all + (size_t)(bg * 2 + 1) * 4096);
        for (int i = tid; i < 2048; i += 256) {
            int half = i >> 10, idx = i & 1023;
            int k = idx >> 4, c4 = (idx & 15) << 2;
            float4 v = half ? wk4[idx] : wq4[idx];
            *(float4*)&region[k * 128 + half * 64 + c4] = v;
        }
    }
    __syncthreads();
    qk_gemm_and_store(At, region, g_q6b[bg], g_k6b[bg], (size_t)blk * 64, tid);
}

// =====================================================================
// Kernel D: pa(s=1)->At + x1 = sigmoid(att@wd1) -> g_x6. grid 3000.
// smem: At[4352] | wd[4096] = 33792 B
// =====================================================================
__global__ void __launch_bounds__(256, 4)
kernelD(const int* __restrict__ n0,
        const int* __restrict__ n1,
        const int* __restrict__ n2,
        const float* __restrict__ wd_all) {
    extern __shared__ float sm[];
    float* At = sm;                  // [64][AT_PITCH]
    float* wd_s = sm + 4352;         // [64][64]
    int tid = threadIdx.x;
    int bg = blockIdx.x / 500;
    int blk = blockIdx.x - bg * 500;
    int gi3 = bg % 3;
    const int* neigh = (gi3 == 0) ? n0 : (gi3 == 1) ? n1 : n2;

    pa_body(g_q6b[bg], g_k6b[bg], neigh, blk, At, tid);
    {
        const float4* wd4 = (const float4*)(wd_all + (size_t)(bg * 2 + 1) * 4096);
        for (int i = tid; i < 1024; i += 256) ((float4*)wd_s)[i] = wd4[i];
    }
    __syncthreads();
    ull accx[4][2];
    x_gemm(At, wd_s, accx, tid);

    int tx = tid & 31, ty = tid >> 5;
    float* xdst = g_x6[bg] + (size_t)blk * 4096;
#pragma unroll
    for (int p = 0; p < 4; p++) {
        int r0 = ty * 8 + 2 * p;
        xdst[(size_t)r0 * 64 + tx]            = sigf(lo32(accx[p][0]));
        xdst[(size_t)(r0 + 1) * 64 + tx]      = sigf(hi32(accx[p][0]));
        xdst[(size_t)r0 * 64 + tx + 32]       = sigf(lo32(accx[p][1]));
        xdst[(size_t)(r0 + 1) * 64 + tx + 32] = sigf(hi32(accx[p][1]));
    }
}

// =====================================================================
// LSTM over L with fused mix: warp per (t,n). grid 500 x 256. (R7)
// =====================================================================
__global__ void lstm_kernel(const float* __restrict__ convw,
                            const float* __restrict__ convb,
                            const float* __restrict__ wmix) {
    __shared__ float cw[4 * 129];
    __shared__ float cb[4];
    __shared__ float wm_s[2 * 192];
    int tid = threadIdx.x;
    for (int i = tid; i < 516; i += 256) cw[i] = convw[i];
    if (tid < 4) cb[tid] = convb[tid];
    if (tid < 128) {
        wm_s[tid] = wmix[tid];
        wm_s[tid + 128] = wmix[tid + 128];
        wm_s[tid + 256] = wmix[tid + 256];
    }
    __syncthreads();
    int gw = blockIdx.x * 8 + (tid >> 5);
    int lane = tid & 31;
    int t = gw / N_, n = gw % N_;
    int b = lane >> 4;
    int dl = (lane & 15) * 4;
    int dbase = b * 64 + dl;
    float wreg[4][4], wh[4], bb[4];
#pragma unroll
    for (int i = 0; i < 4; i++) {
#pragma unroll
        for (int q = 0; q < 4; q++) wreg[i][q] = cw[i * 129 + dbase + q];
        wh[i] = cw[i * 129 + 128];
        bb[i] = cb[i];
    }
    const float* wm = wm_s + b * 192;
    float4 m0 = *(const float4*)&wm[dl];
    float4 m1 = *(const float4*)&wm[64 + dl];
    float4 m2 = *(const float4*)&wm[128 + dl];

    float h = 0.f, c = 0.f;
    for (int l = 0; l < L_; l++) {
        size_t off = (((size_t)t * L_ + l) * N_ + n) * 64 + dl;
        float4 x0 = *(const float4*)&g_x6[b * 3 + 0][off];
        float4 x1 = *(const float4*)&g_x6[b * 3 + 1][off];
        float4 x2 = *(const float4*)&g_x6[b * 3 + 2][off];
        float4 xin;
        xin.x = sigf(x0.x * m0.x + x1.x * m1.x + x2.x * m2.x);
        xin.y = sigf(x0.y * m0.y + x1.y * m1.y + x2.y * m2.y);
        xin.z = sigf(x0.z * m0.z + x1.z * m1.z + x2.z * m2.z);
        xin.w = sigf(x0.w * m0.w + x1.w * m1.w + x2.w * m2.w);
        float s[4];
#pragma unroll
        for (int i = 0; i < 4; i++) {
            s[i] = xin.x * wreg[i][0] + xin.y * wreg[i][1] +
                   xin.z * wreg[i][2] + xin.w * wreg[i][3];
#pragma unroll
            for (int o = 16; o; o >>= 1)
                s[i] += __shfl_xor_sync(0xffffffffu, s[i], o);
        }
        float gi = sigf(s[0] + h * wh[0] + bb[0]);
        float gf = sigf(s[1] + h * wh[1] + bb[1]);
        float go = sigf(s[2] + h * wh[2] + bb[2]);
        float gg = tanhf(s[3] + h * wh[3] + bb[3]);
        c = gf * c + gi * gg;
        h = go * tanhf(c);
    }
    if (lane == 0) g_h[t * N_ + n] = h;
}

// =====================================================================
// final projection: grid T_, block 512
// =====================================================================
__global__ void final_kernel(const float* __restrict__ finw,
                             const float* __restrict__ finb,
                             float* __restrict__ out) {
    __shared__ float hs[500];
    int t = blockIdx.x, tid = threadIdx.x;
    if (tid < 500) hs[tid] = g_h[t * N_ + tid];
    __syncthreads();
    if (tid < 500) {
        float acc = finb[tid];
        const float4* wr = (const float4*)(finw + (size_t)tid * 500);
#pragma unroll 5
        for (int m4 = 0; m4 < 125; m4++) {
            float4 wv = wr[m4];
            acc = fmaf(hs[m4 * 4 + 0], wv.x, acc);
            acc = fmaf(hs[m4 * 4 + 1], wv.y, acc);
            acc = fmaf(hs[m4 * 4 + 2], wv.z, acc);
            acc = fmaf(hs[m4 * 4 + 3], wv.w, acc);
        }
        out[t * N_ + tid] = sigf(acc);
    }
}

// ---------------- launcher ----------------
extern "C" void kernel_launch(void* const* d_in, const int* in_sizes, int n_in,
                              void* d_out, int out_size) {
    const float* stat = (const float*)d_in[0];
    const float* thre = (const float*)d_in[1];
    const float* dynn = (const float*)d_in[2];
    const int* npoi = (const int*)d_in[3];
    const int* nroad = (const int*)d_in[4];
    const int* nrec = (const int*)d_in[5];
    const float* w1 = (const float*)d_in[6];
    const float* wq = (const float*)d_in[7];
    const float* wk = (const float*)d_in[8];
    const float* wdm = (const float*)d_in[9];
    const float* wmix = (const float*)d_in[10];
    const float* convw = (const float*)d_in[11];
    const float* convb = (const float*)d_in[12];
    const float* finw = (const float*)d_in[13];
    const float* finb = (const float*)d_in[14];

    float* out = (float*)d_out;
    float* out_scores = out;                          // (T,N)       4000
    float* out_nowfinal = out + T_ * N_;              // (L,N,D)     256000
    float* out_diffs = out + T_ * N_ + L_ * N_ * D_;  // (T-1,L,N,D) 1792000

    cudaFuncSetAttribute(kernelA,
                         cudaFuncAttributeMaxDynamicSharedMemorySize, P1_SMEM);
    cudaFuncSetAttribute(kernelB,
                         cudaFuncAttributeMaxDynamicSharedMemorySize, P1_SMEM);
    cudaFuncSetAttribute(kernelC,
                         cudaFuncAttributeMaxDynamicSharedMemorySize, P1_SMEM);
    cudaFuncSetAttribute(kernelD,
                         cudaFuncAttributeMaxDynamicSharedMemorySize, PD_SMEM);

    kernelA<<<1750, 256, P1_SMEM>>>(stat, thre, dynn, w1, wq, wk,
                                    out_nowfinal, out_diffs);   // evo + pass1_sta
    kernelB<<<1500, 256, P1_SMEM>>>(wq, wk);                    // pass1_dyn
    kernelC<<<3000, 256, P1_SMEM>>>(npoi, nroad, nrec, wdm, wq, wk);
    kernelD<<<3000, 256, PD_SMEM>>>(npoi, nroad, nrec, wdm);
    lstm_kernel<<<500, 256>>>(convw, convb, wmix);
    final_kernel<<<T_, 512>>>(finw, finb, out_scores);
}

// round 17
// speedup vs baseline: 1.3349x; 1.0163x over previous
#include <cuda_runtime.h>
#include <cuda_bf16.h>
#include <cstdint>

// Problem constants
#define T_ 8
#define L_ 8
#define N_ 500
#define D_ 64
#define K_ 12
#define S_ 2
#define RLN (L_*N_)          // 4000
#define R_ (T_*L_*N_)        // 32000 rows of (t,l,n)
#define ELEMS (R_*D_)        // 2048000

typedef unsigned long long ull;

// ---------------- scratch buffers (no allocation allowed) ----------------
__device__ float g_dyn[ELEMS];          // all_dyn (T,L,N,D)
__device__ float g_q6[6][ELEMS];        // stage-0 q
__device__ float g_k6[6][ELEMS];        // stage-0 k
__device__ float g_q6b[6][ELEMS];       // stage-1 q
__device__ float g_k6b[6][ELEMS];       // stage-1 k
__device__ float g_x6[6][ELEMS];        // final attention output
__device__ float g_h[T_*N_];            // LSTM h_last

__device__ __forceinline__ float sigf(float x) {
    return 1.f / (1.f + __expf(-x));
}

__device__ __forceinline__ void fma2(ull& acc, ull a, ull b) {
    asm("fma.rn.f32x2 %0, %1, %2, %0;" : "+l"(acc) : "l"(a), "l"(b));
}
__device__ __forceinline__ float lo32(ull v) { return __uint_as_float((unsigned)v); }
__device__ __forceinline__ float hi32(ull v) { return __uint_as_float((unsigned)(v >> 32)); }
__device__ __forceinline__ ull dup2(float a) {
    ull r; unsigned u = __float_as_uint(a);
    asm("mov.b64 %0, {%1, %1};" : "=l"(r) : "r"(u));
    return r;
}

// =====================================================================
// shared device bodies
// =====================================================================
#define AT_PITCH 68
// pass1/kernelC smem: At[64*68]=4352 + W[64*128]=8192 -> 12544 floats
#define P1_SMEM (12544 * 4)     // 50176
// kernelD smem: At 4352 + wd 4096 -> 8448 floats
#define PD_SMEM (8448 * 4)      // 33792

// q/k GEMM inner (R4 frozen loop, W pitch 128). At ready, W_s ready.
__device__ __forceinline__ void qk_gemm_and_store(
    const float* At, const float* W_s, float* qdst, float* kdst,
    size_t rowbase, int tid) {
    int tx = tid & 31, ty = tid >> 5;
    ull acc[8][2];
#pragma unroll
    for (int r = 0; r < 8; r++) { acc[r][0] = 0ull; acc[r][1] = 0ull; }
#pragma unroll 4
    for (int k = 0; k < 64; k++) {
        float4 a0 = *(const float4*)&At[k * AT_PITCH + ty * 8];
        float4 a1 = *(const float4*)&At[k * AT_PITCH + ty * 8 + 4];
        const ull* wrow = (const ull*)&W_s[k * 128];
        ull wq2 = wrow[tx];
        ull wk2 = wrow[tx + 32];
        ull ad[8];
        ad[0] = dup2(a0.x); ad[1] = dup2(a0.y); ad[2] = dup2(a0.z); ad[3] = dup2(a0.w);
        ad[4] = dup2(a1.x); ad[5] = dup2(a1.y); ad[6] = dup2(a1.z); ad[7] = dup2(a1.w);
#pragma unroll
        for (int r = 0; r < 8; r++) {
            fma2(acc[r][0], ad[r], wq2);
            fma2(acc[r][1], ad[r], wk2);
        }
    }
#pragma unroll
    for (int r = 0; r < 8; r++) {
        size_t ro = (rowbase + r) * 64 + 2 * tx;
        *(float2*)&qdst[ro] = make_float2(lo32(acc[r][0]), hi32(acc[r][0]));
        *(float2*)&kdst[ro] = make_float2(lo32(acc[r][1]), hi32(acc[r][1]));
    }
}

// pass1 body: direct transposed load of X + W load + GEMM
__device__ __forceinline__ void pass1_body(
    const float* __restrict__ x, const float* __restrict__ wq,
    const float* __restrict__ wk, float* qdst, float* kdst,
    size_t rowbase, float* sm, int tid) {
    float* At = sm;                 // [64][AT_PITCH]
    float* W_s = sm + 4352;         // [64][128]
    for (int i = tid; i < 4096; i += 256) {
        int row = i >> 6, k = i & 63;
        At[k * AT_PITCH + row] = x[i];    // direct transpose
    }
    {
        const float4* wq4 = (const float4*)wq;
        const float4* wk4 = (const float4*)wk;
        for (int i = tid; i < 2048; i += 256) {
            int half = i >> 10, idx = i & 1023;
            int k = idx >> 4, c4 = (idx & 15) << 2;
            float4 v = half ? wk4[idx] : wq4[idx];
            *(float4*)&W_s[k * 128 + half * 64 + c4] = v;
        }
    }
    __syncthreads();
    qk_gemm_and_store(At, W_s, qdst, kdst, rowbase, tid);
}

// pa body, one-pass no-max softmax; att stored transposed with a
// BANK-PERMUTED row order: At row sigma(k) holds att column k,
// sigma(k) = (k&3)*16 + (k>>2)  ->  STS bank stride 4 (2-way) not 16-way.
__device__ __forceinline__ void pa_body(
    const float* __restrict__ qsrc, const float* __restrict__ ksrc,
    const int* __restrict__ neigh, int blk, float* At, int tid) {
    int w = tid >> 5, lane = tid & 31;
    int half = lane >> 4, l16 = lane & 15;
#pragma unroll
    for (int it = 0; it < 4; it++) {
        int r = w * 8 + it * 2 + half;
        int rowid = blk * 64 + r;
        int tl = rowid / N_;
        int n = rowid - tl * N_;
        const float* qb = qsrc + (size_t)tl * N_ * 64;
        const float* kb = ksrc + (size_t)tl * N_ * 64;
        float4 q = *(const float4*)&qb[(size_t)n * 64 + l16 * 4];

        float ssum = 0.f;
        float4 o = make_float4(0.f, 0.f, 0.f, 0.f);
#pragma unroll
        for (int j = 0; j < K_; j++) {
            int nb = __ldg(&neigh[n * K_ + j]);
            float4 kv = __ldg((const float4*)&kb[(size_t)nb * 64 + l16 * 4]);
            float d = q.x * kv.x + q.y * kv.y + q.z * kv.z + q.w * kv.w;
            d += __shfl_xor_sync(0xffffffffu, d, 8);
            d += __shfl_xor_sync(0xffffffffu, d, 4);
            d += __shfl_xor_sync(0xffffffffu, d, 2);
            d += __shfl_xor_sync(0xffffffffu, d, 1);
            float wj = __expf(d);
            ssum += wj;
            o.x = fmaf(wj, kv.x, o.x);
            o.y = fmaf(wj, kv.y, o.y);
            o.z = fmaf(wj, kv.z, o.z);
            o.w = fmaf(wj, kv.w, o.w);
        }
        float inv = 1.f / ssum;
        // sigma(l16*4+c) = c*16 + l16
        At[(0 * 16 + l16) * AT_PITCH + r] = fmaf(o.x, inv, q.x);
        At[(1 * 16 + l16) * AT_PITCH + r] = fmaf(o.y, inv, q.y);
        At[(2 * 16 + l16) * AT_PITCH + r] = fmaf(o.z, inv, q.z);
        At[(3 * 16 + l16) * AT_PITCH + r] = fmaf(o.w, inv, q.w);
    }
}

// permuted wd loader: wd_s row j gets wd row sigma^{-1}(j) = (j&15)*4+(j>>4)
__device__ __forceinline__ void load_wd_perm(
    float* wd_s, const float* __restrict__ wd, int tid) {
    const float4* wd4 = (const float4*)wd;
    for (int i = tid; i < 1024; i += 256) {
        int j = i >> 4, c4 = i & 15;
        int prow = (j & 15) * 4 + (j >> 4);
        *(float4*)&wd_s[j * 64 + c4 * 4] = wd4[prow * 16 + c4];
    }
}

// x-GEMM (R8 v1 frozen loop); At rows permuted, wd_s rows permuted same way
__device__ __forceinline__ void x_gemm(
    const float* At, const float* wd_s, ull accx[4][2], int tid) {
    int tx = tid & 31, ty = tid >> 5;
#pragma unroll
    for (int p = 0; p < 4; p++) { accx[p][0] = 0ull; accx[p][1] = 0ull; }
#pragma unroll 4
    for (int k = 0; k < 64; k++) {
        const ulonglong2* ar = (const ulonglong2*)(At + k * AT_PITCH + ty * 8);
        ulonglong2 a01 = ar[0];
        ulonglong2 a23 = ar[1];
        ull w0 = dup2(wd_s[k * 64 + tx]);
        ull w1 = dup2(wd_s[k * 64 + tx + 32]);
        fma2(accx[0][0], a01.x, w0); fma2(accx[0][1], a01.x, w1);
        fma2(accx[1][0], a01.y, w0); fma2(accx[1][1], a01.y, w1);
        fma2(accx[2][0], a23.x, w0); fma2(accx[2][1], a23.x, w1);
        fma2(accx[3][0], a23.y, w0); fma2(accx[3][1], a23.y, w1);
    }
}

// =====================================================================
// Kernel A: blocks 0-249 evo; blocks 250-1749 pass1 for sta (bg 3-5)
// =====================================================================
__global__ void __launch_bounds__(256)
kernelA(const float* __restrict__ stat,
        const float* __restrict__ thre,
        const float* __restrict__ dynn,
        const float* __restrict__ w1,
        const float* __restrict__ wq_all,
        const float* __restrict__ wk_all,
        float* __restrict__ out_nowfinal,
        float* __restrict__ out_diffs) {
    extern __shared__ float sm[];
    int tid = threadIdx.x;
    if (blockIdx.x >= 250) {
        int gblk = blockIdx.x - 250;
        int bg = 3 + gblk / 500;
        int blk = gblk - (bg - 3) * 500;
        pass1_body(stat + (size_t)blk * 4096,
                   wq_all + (size_t)(bg * 2) * 4096,
                   wk_all + (size_t)(bg * 2) * 4096,
                   g_q6[bg], g_k6[bg], (size_t)blk * 64, sm, tid);
        return;
    }
    // ---- evo ----
    float* w1_s = sm;                            // [8192]
    float (*now_s)[64] = (float(*)[64])(sm + 8192);
    float (*st_s)[64] = (float(*)[64])(sm + 9216);
    float* th_s = sm + 10240;                    // [16]
    for (int i = tid; i < 8192; i += 256) w1_s[i] = w1[i];
    int e = tid & 63, grp = tid >> 6;
    int row0 = blockIdx.x * 16;
#pragma unroll
    for (int i = 0; i < 4; i++) {
        int r = grp * 4 + i;
        float v = dynn[(size_t)(row0 + r) * 64 + e];
        now_s[r][e] = v;
        g_dyn[(size_t)(row0 + r) * 64 + e] = v;
    }
    __syncthreads();
    for (int t = 1; t < T_; t++) {
        size_t base = (size_t)t * RLN + row0;
        ((float4*)st_s)[tid] = ((const float4*)(stat + base * 64))[tid];
        if (tid < 16) th_s[tid] = thre[base + tid];
        __syncthreads();
        float sum[4] = {0.f, 0.f, 0.f, 0.f};
#pragma unroll 4
        for (int d = 0; d < 64; d += 4) {
            float wn0 = w1_s[(d + 0) * 64 + e];
            float wn1 = w1_s[(d + 1) * 64 + e];
            float wn2 = w1_s[(d + 2) * 64 + e];
            float wn3 = w1_s[(d + 3) * 64 + e];
            float ws0 = w1_s[(64 + d + 0) * 64 + e];
            float ws1 = w1_s[(64 + d + 1) * 64 + e];
            float ws2 = w1_s[(64 + d + 2) * 64 + e];
            float ws3 = w1_s[(64 + d + 3) * 64 + e];
#pragma unroll
            for (int i = 0; i < 4; i++) {
                int r = grp * 4 + i;
                float4 nv = *(float4*)&now_s[r][d];
                float4 sv = *(float4*)&st_s[r][d];
                sum[i] = fmaf(nv.x, wn0, sum[i]); sum[i] = fmaf(nv.y, wn1, sum[i]);
                sum[i] = fmaf(nv.z, wn2, sum[i]); sum[i] = fmaf(nv.w, wn3, sum[i]);
                sum[i] = fmaf(sv.x, ws0, sum[i]); sum[i] = fmaf(sv.y, ws1, sum[i]);
                sum[i] = fmaf(sv.z, ws2, sum[i]); sum[i] = fmaf(sv.w, ws3, sum[i]);
            }
        }
        float vals[4];
#pragma unroll
        for (int i = 0; i < 4; i++) {
            int r = grp * 4 + i;
            float th = th_s[r];
            float nv = now_s[r][e];
            float val = sigf(sum[i] * th + nv * (1.f - th));
            vals[i] = val;
            g_dyn[(base + r) * 64 + e] = val;
            out_diffs[((size_t)(t - 1) * RLN + row0 + r) * 64 + e] = val - nv;
            if (t == T_ - 1) out_nowfinal[(size_t)(row0 + r) * 64 + e] = val;
        }
        __syncthreads();
#pragma unroll
        for (int i = 0; i < 4; i++) now_s[grp * 4 + i][e] = vals[i];
        __syncthreads();
    }
}

// =====================================================================
// Kernel B: pass1 for dyn (bg 0-2). grid 1500.
// =====================================================================
__global__ void __launch_bounds__(256)
kernelB(const float* __restrict__ wq_all,
        const float* __restrict__ wk_all) {
    extern __shared__ float sm[];
    int tid = threadIdx.x;
    int bg = blockIdx.x / 500;
    int blk = blockIdx.x - bg * 500;
    pass1_body((const float*)g_dyn + (size_t)blk * 4096,
               wq_all + (size_t)(bg * 2) * 4096,
               wk_all + (size_t)(bg * 2) * 4096,
               g_q6[bg], g_k6[bg], (size_t)blk * 64, sm, tid);
}

// =====================================================================
// Kernel C: pa(s=0)->At(perm) + x0 = sigmoid(att@wd0) + qk GEMM(s=1).
// grid 3000. __launch_bounds__(256,4). smem: At[4352] | region[8192]
// =====================================================================
__global__ void __launch_bounds__(256, 4)
kernelC(const int* __restrict__ n0,
        const int* __restrict__ n1,
        const int* __restrict__ n2,
        const float* __restrict__ wd_all,
        const float* __restrict__ wq_all,
        const float* __restrict__ wk_all) {
    extern __shared__ float sm[];
    float* At = sm;                  // [64][AT_PITCH]
    float* region = sm + 4352;       // wd[4096] then W_s[8192]
    float* wd_s = region;            // [64][64]
    int tid = threadIdx.x;
    int bg = blockIdx.x / 500;
    int blk = blockIdx.x - bg * 500;
    int gi3 = bg % 3;
    const int* neigh = (gi3 == 0) ? n0 : (gi3 == 1) ? n1 : n2;

    pa_body(g_q6[bg], g_k6[bg], neigh, blk, At, tid);   // att -> At (permuted)
    load_wd_perm(wd_s, wd_all + (size_t)(bg * 2) * 4096, tid);
    __syncthreads();
    ull accx[4][2];
    x_gemm(At, wd_s, accx, tid);
    __syncthreads();
    // phase 4: xT -> At (natural k-order; At fully rewritten) ; wq1/wk1 -> region
    int tx = tid & 31, ty = tid >> 5;
#pragma unroll
    for (int p = 0; p < 4; p++) {
        int r0 = ty * 8 + 2 * p;
        *(float2*)&At[tx * AT_PITCH + r0] =
            make_float2(sigf(lo32(accx[p][0])), sigf(hi32(accx[p][0])));
        *(float2*)&At[(tx + 32) * AT_PITCH + r0] =
            make_float2(sigf(lo32(accx[p][1])), sigf(hi32(accx[p][1])));
    }
    {
        const float4* wq4 = (const float4*)(wq_all + (size_t)(bg * 2 + 1) * 4096);
        const float4* wk4 = (const float4*)(wk_all + (size_t)(bg * 2 + 1) * 4096);
        for (int i = tid; i < 2048; i += 256) {
            int half = i >> 10, idx = i & 1023;
            int k = idx >> 4, c4 = (idx & 15) << 2;
            float4 v = half ? wk4[idx] : wq4[idx];
            *(float4*)&region[k * 128 + half * 64 + c4] = v;
        }
    }
    __syncthreads();
    qk_gemm_and_store(At, region, g_q6b[bg], g_k6b[bg], (size_t)blk * 64, tid);
}

// =====================================================================
// Kernel D: pa(s=1)->At(perm) + x1 = sigmoid(att@wd1) -> g_x6. grid 3000.
// =====================================================================
__global__ void __launch_bounds__(256, 4)
kernelD(const int* __restrict__ n0,
        const int* __restrict__ n1,
        const int* __restrict__ n2,
        const float* __restrict__ wd_all) {
    extern __shared__ float sm[];
    float* At = sm;                  // [64][AT_PITCH]
    float* wd_s = sm + 4352;         // [64][64]
    int tid = threadIdx.x;
    int bg = blockIdx.x / 500;
    int blk = blockIdx.x - bg * 500;
    int gi3 = bg % 3;
    const int* neigh = (gi3 == 0) ? n0 : (gi3 == 1) ? n1 : n2;

    pa_body(g_q6b[bg], g_k6b[bg], neigh, blk, At, tid);
    load_wd_perm(wd_s, wd_all + (size_t)(bg * 2 + 1) * 4096, tid);
    __syncthreads();
    ull accx[4][2];
    x_gemm(At, wd_s, accx, tid);

    int tx = tid & 31, ty = tid >> 5;
    float* xdst = g_x6[bg] + (size_t)blk * 4096;
#pragma unroll
    for (int p = 0; p < 4; p++) {
        int r0 = ty * 8 + 2 * p;
        xdst[(size_t)r0 * 64 + tx]            = sigf(lo32(accx[p][0]));
        xdst[(size_t)(r0 + 1) * 64 + tx]      = sigf(hi32(accx[p][0]));
        xdst[(size_t)r0 * 64 + tx + 32]       = sigf(lo32(accx[p][1]));
        xdst[(size_t)(r0 + 1) * 64 + tx + 32] = sigf(hi32(accx[p][1]));
    }
}

// =====================================================================
// LSTM over L with fused mix: warp per (t,n). grid 500 x 256. (R7)
// =====================================================================
__global__ void lstm_kernel(const float* __restrict__ convw,
                            const float* __restrict__ convb,
                            const float* __restrict__ wmix) {
    __shared__ float cw[4 * 129];
    __shared__ float cb[4];
    __shared__ float wm_s[2 * 192];
    int tid = threadIdx.x;
    for (int i = tid; i < 516; i += 256) cw[i] = convw[i];
    if (tid < 4) cb[tid] = convb[tid];
    if (tid < 128) {
        wm_s[tid] = wmix[tid];
        wm_s[tid + 128] = wmix[tid + 128];
        wm_s[tid + 256] = wmix[tid + 256];
    }
    __syncthreads();
    int gw = blockIdx.x * 8 + (tid >> 5);
    int lane = tid & 31;
    int t = gw / N_, n = gw % N_;
    int b = lane >> 4;
    int dl = (lane & 15) * 4;
    int dbase = b * 64 + dl;
    float wreg[4][4], wh[4], bb[4];
#pragma unroll
    for (int i = 0; i < 4; i++) {
#pragma unroll
        for (int q = 0; q < 4; q++) wreg[i][q] = cw[i * 129 + dbase + q];
        wh[i] = cw[i * 129 + 128];
        bb[i] = cb[i];
    }
    const float* wm = wm_s + b * 192;
    float4 m0 = *(const float4*)&wm[dl];
    float4 m1 = *(const float4*)&wm[64 + dl];
    float4 m2 = *(const float4*)&wm[128 + dl];

    float h = 0.f, c = 0.f;
    for (int l = 0; l < L_; l++) {
        size_t off = (((size_t)t * L_ + l) * N_ + n) * 64 + dl;
        float4 x0 = *(const float4*)&g_x6[b * 3 + 0][off];
        float4 x1 = *(const float4*)&g_x6[b * 3 + 1][off];
        float4 x2 = *(const float4*)&g_x6[b * 3 + 2][off];
        float4 xin;
        xin.x = sigf(x0.x * m0.x + x1.x * m1.x + x2.x * m2.x);
        xin.y = sigf(x0.y * m0.y + x1.y * m1.y + x2.y * m2.y);
        xin.z = sigf(x0.z * m0.z + x1.z * m1.z + x2.z * m2.z);
        xin.w = sigf(x0.w * m0.w + x1.w * m1.w + x2.w * m2.w);
        float s[4];
#pragma unroll
        for (int i = 0; i < 4; i++) {
            s[i] = xin.x * wreg[i][0] + xin.y * wreg[i][1] +
                   xin.z * wreg[i][2] + xin.w * wreg[i][3];
#pragma unroll
            for (int o = 16; o; o >>= 1)
                s[i] += __shfl_xor_sync(0xffffffffu, s[i], o);
        }
        float gi = sigf(s[0] + h * wh[0] + bb[0]);
        float gf = sigf(s[1] + h * wh[1] + bb[1]);
        float go = sigf(s[2] + h * wh[2] + bb[2]);
        float gg = tanhf(s[3] + h * wh[3] + bb[3]);
        c = gf * c + gi * gg;
        h = go * tanhf(c);
    }
    if (lane == 0) g_h[t * N_ + n] = h;
}

// =====================================================================
// final projection: grid T_, block 512
// =====================================================================
__global__ void final_kernel(const float* __restrict__ finw,
                             const float* __restrict__ finb,
                             float* __restrict__ out) {
    __shared__ float hs[500];
    int t = blockIdx.x, tid = threadIdx.x;
    if (tid < 500) hs[tid] = g_h[t * N_ + tid];
    __syncthreads();
    if (tid < 500) {
        float acc = finb[tid];
        const float4* wr = (const float4*)(finw + (size_t)tid * 500);
#pragma unroll 5
        for (int m4 = 0; m4 < 125; m4++) {
            float4 wv = wr[m4];
            acc = fmaf(hs[m4 * 4 + 0], wv.x, acc);
            acc = fmaf(hs[m4 * 4 + 1], wv.y, acc);
            acc = fmaf(hs[m4 * 4 + 2], wv.z, acc);
            acc = fmaf(hs[m4 * 4 + 3], wv.w, acc);
        }
        out[t * N_ + tid] = sigf(acc);
    }
}

// ---------------- launcher ----------------
extern "C" void kernel_launch(void* const* d_in, const int* in_sizes, int n_in,
                              void* d_out, int out_size) {
    const float* stat = (const float*)d_in[0];
    const float* thre = (const float*)d_in[1];
    const float* dynn = (const float*)d_in[2];
    const int* npoi = (const int*)d_in[3];
    const int* nroad = (const int*)d_in[4];
    const int* nrec = (const int*)d_in[5];
    const float* w1 = (const float*)d_in[6];
    const float* wq = (const float*)d_in[7];
    const float* wk = (const float*)d_in[8];
    const float* wdm = (const float*)d_in[9];
    const float* wmix = (const float*)d_in[10];
    const float* convw = (const float*)d_in[11];
    const float* convb = (const float*)d_in[12];
    const float* finw = (const float*)d_in[13];
    const float* finb = (const float*)d_in[14];

    float* out = (float*)d_out;
    float* out_scores = out;                          // (T,N)       4000
    float* out_nowfinal = out + T_ * N_;              // (L,N,D)     256000
    float* out_diffs = out + T_ * N_ + L_ * N_ * D_;  // (T-1,L,N,D) 1792000

    cudaFuncSetAttribute(kernelA,
                         cudaFuncAttributeMaxDynamicSharedMemorySize, P1_SMEM);
    cudaFuncSetAttribute(kernelB,
                         cudaFuncAttributeMaxDynamicSharedMemorySize, P1_SMEM);
    cudaFuncSetAttribute(kernelC,
                         cudaFuncAttributeMaxDynamicSharedMemorySize, P1_SMEM);
    cudaFuncSetAttribute(kernelD,
                         cudaFuncAttributeMaxDynamicSharedMemorySize, PD_SMEM);

    kernelA<<<1750, 256, P1_SMEM>>>(stat, thre, dynn, w1, wq, wk,
                                    out_nowfinal, out_diffs);   // evo + pass1_sta
    kernelB<<<1500, 256, P1_SMEM>>>(wq, wk);                    // pass1_dyn
    kernelC<<<3000, 256, P1_SMEM>>>(npoi, nroad, nrec, wdm, wq, wk);
    kernelD<<<3000, 256, PD_SMEM>>>(npoi, nroad, nrec, wdm);
    lstm_kernel<<<500, 256>>>(convw, convb, wmix);
    final_kernel<<<T_, 512>>>(finw, finb, out_scores);
}